// round 3
// baseline (speedup 1.0000x reference)
#include <cuda_runtime.h>
#include <cuda_bf16.h>
#include <cstdint>

#define D      512
#define NWAY   64
#define KSHOT  16
#define MAXQ   8192
#define NBROWS 576          // 512 W rows + 64 R rows
#define SA     72           // smem K-stride (bf16): 144B rows, conflict-free frag loads
#define ASZ    (128 * SA)   // A stage elems
#define BSZ    (64 * SA)    // B stage elems

// ---------------- device scratch ----------------
__device__ float          g_smean[NWAY * D];
__device__ float          g_pfp32[NWAY * D];
__device__ float          g_pcterm[NWAY];            // ||p||^2 - 2 b.p
__device__ __nv_bfloat16  g_qbf[(size_t)MAXQ * D];
__device__ __nv_bfloat16  g_Bbig[NBROWS * D];        // rows 0..511 = W(bf16), 512..575 = R(bf16)
__device__ float          g_partial[(size_t)MAXQ * 8];
__device__ float          g_cross[(size_t)MAXQ * NWAY];

// ---------------- helpers ----------------
__device__ __forceinline__ void mma16816(float* c,
                                         uint32_t a0, uint32_t a1, uint32_t a2, uint32_t a3,
                                         uint32_t b0, uint32_t b1) {
    asm volatile(
        "mma.sync.aligned.m16n8k16.row.col.f32.bf16.bf16.f32 "
        "{%0,%1,%2,%3},{%4,%5,%6,%7},{%8,%9},{%0,%1,%2,%3};\n"
        : "+f"(c[0]), "+f"(c[1]), "+f"(c[2]), "+f"(c[3])
        : "r"(a0), "r"(a1), "r"(a2), "r"(a3), "r"(b0), "r"(b1));
}

__device__ __forceinline__ void cp_async16(void* smem, const void* gmem) {
    uint32_t s = (uint32_t)__cvta_generic_to_shared(smem);
    asm volatile("cp.async.cg.shared.global [%0], [%1], 16;\n" :: "r"(s), "l"(gmem));
}
#define CP_COMMIT() asm volatile("cp.async.commit_group;\n")
#define CP_WAIT(n)  asm volatile("cp.async.wait_group %0;\n" :: "n"(n))

// ---------------- prep: Q->bf16, W->bf16 (into g_Bbig), class means ----------------
__global__ void prep_kernel(const float* __restrict__ q, const float* __restrict__ W,
                            const float* __restrict__ support, int qblocks, int M) {
    int b = blockIdx.x;
    if (b < qblocks) {
        size_t total = (size_t)M * D;
        size_t base = (size_t)b * 2048 + threadIdx.x * 8;
        if (base + 8 <= total) {
            float4 v0 = *(const float4*)(q + base);
            float4 v1 = *(const float4*)(q + base + 4);
            __nv_bfloat162 p0 = __floats2bfloat162_rn(v0.x, v0.y);
            __nv_bfloat162 p1 = __floats2bfloat162_rn(v0.z, v0.w);
            __nv_bfloat162 p2 = __floats2bfloat162_rn(v1.x, v1.y);
            __nv_bfloat162 p3 = __floats2bfloat162_rn(v1.z, v1.w);
            uint4 o;
            o.x = *(uint32_t*)&p0; o.y = *(uint32_t*)&p1;
            o.z = *(uint32_t*)&p2; o.w = *(uint32_t*)&p3;
            *(uint4*)(g_qbf + base) = o;
        } else {
            for (int e = 0; e < 8; e++)
                if (base + e < total) g_qbf[base + e] = __float2bfloat16(q[base + e]);
        }
    } else if (b < qblocks + 256) {
        int base = (b - qblocks) * 1024 + threadIdx.x * 4;   // W: 262144 elems
        float4 v = *(const float4*)(W + base);
        *(__nv_bfloat162*)(g_Bbig + base)     = __floats2bfloat162_rn(v.x, v.y);
        *(__nv_bfloat162*)(g_Bbig + base + 2) = __floats2bfloat162_rn(v.z, v.w);
    } else {
        int c = b - qblocks - 256;
        for (int col = threadIdx.x; col < D; col += blockDim.x) {
            float s = 0.f;
            #pragma unroll
            for (int k = 0; k < KSHOT; k++) s += support[(size_t)(c * KSHOT + k) * D + col];
            g_smean[c * D + col] = s * (1.f / KSHOT);
        }
    }
}

// ---------------- prototypes = smean @ W^T + b (fp32) ----------------
__global__ void proto_proj_kernel(const float* __restrict__ W, const float* __restrict__ bias) {
    __shared__ float sW[4][D + 8];
    int nb = blockIdx.x * 4;
    for (int i = threadIdx.x; i < 4 * D; i += blockDim.x) {
        int n = i >> 9, k = i & (D - 1);
        sW[n][k] = W[(size_t)(nb + n) * D + k];
    }
    __syncthreads();
    for (int o = threadIdx.x; o < NWAY * 4; o += blockDim.x) {
        int c = o >> 2, nl = o & 3;
        const float* s = g_smean + c * D;
        float acc = 0.f;
        #pragma unroll 8
        for (int k = 0; k < D; k++) acc += s[k] * sW[nl][k];
        g_pfp32[c * D + nb + nl] = acc + bias[nb + nl];
    }
}

// ---------------- pcterm[c] = ||p_c||^2 - 2 b.p_c  (fp32 exact) ----------------
__global__ void proto_norm_kernel(const float* __restrict__ bias) {
    int c = blockIdx.x;
    float p = 0.f, db = 0.f;
    for (int k = threadIdx.x; k < D; k += blockDim.x) {
        float v = g_pfp32[c * D + k];
        p += v * v;
        db += bias[k] * v;
    }
    __shared__ float redp[4], redb[4];
    #pragma unroll
    for (int o = 16; o > 0; o >>= 1) {
        p  += __shfl_xor_sync(0xffffffffu, p, o);
        db += __shfl_xor_sync(0xffffffffu, db, o);
    }
    if ((threadIdx.x & 31) == 0) { redp[threadIdx.x >> 5] = p; redb[threadIdx.x >> 5] = db; }
    __syncthreads();
    if (threadIdx.x == 0)
        g_pcterm[c] = (redp[0] + redp[1] + redp[2] + redp[3])
                      - 2.f * (redb[0] + redb[1] + redb[2] + redb[3]);
}

// ---------------- R = P_proj @ W  -> g_Bbig rows 512..575 (bf16) ----------------
// grid (4, 32): 16 classes x 16 k-cols per block
__global__ void r_kernel(const float* __restrict__ W) {
    __shared__ float sp[16 * D];       // 32KB
    __shared__ float sw[D * 16];       // 32KB
    int tid = threadIdx.x;
    int c0 = blockIdx.x * 16, k0 = blockIdx.y * 16;
    for (int i = tid; i < 16 * D; i += 256) {
        int r = i >> 9, col = i & (D - 1);
        sp[r * D + col] = g_pfp32[(size_t)(c0 + r) * D + col];
    }
    for (int i = tid; i < D * 16; i += 256) {
        int n = i >> 4, k = i & 15;
        sw[n * 16 + k] = W[(size_t)n * D + k0 + k];
    }
    __syncthreads();
    int c = tid >> 4, k = tid & 15;
    float acc = 0.f;
    #pragma unroll 8
    for (int n = 0; n < D; n++) acc += sp[c * D + n] * sw[n * 16 + k];
    g_Bbig[(size_t)(512 + c0 + c) * D + k0 + k] = __float2bfloat16(acc);
}

// ---------------- main GEMM: C = Qbf @ Bbig^T, custom epilogues ----------------
// CTA tile 128(M) x 64(N), K=512, 3-stage cp.async. grid (M/128, 9).
// ntile 0..7: norm partials sum((c+bias)^2) -> g_partial. ntile 8: cross -> g_cross.
#define SM_BIAS  (3 * (ASZ + BSZ) * 2)
#define SM_NORM  (SM_BIAS + 64 * 4)
#define SM_MAIN  (SM_NORM + 128 * 2 * 4)

__global__ __launch_bounds__(256, 2) void main_gemm(const float* __restrict__ bias, int M) {
    extern __shared__ char sm[];
    __nv_bfloat16* sA = (__nv_bfloat16*)sm;                     // 3 stages 128xSA
    __nv_bfloat16* sB = (__nv_bfloat16*)sm + 3 * ASZ;           // 3 stages 64xSA
    float* sbias = (float*)(sm + SM_BIAS);
    float* snorm = (float*)(sm + SM_NORM);

    int tid = threadIdx.x;
    int m0 = blockIdx.x * 128;
    int nt = blockIdx.y;
    int n0 = nt * 64;
    int warp = tid >> 5, lane = tid & 31;
    int wm = warp & 3, wn = warp >> 2;        // 4(M) x 2(N) warps; warp tile 32x32
    int g = lane >> 2, t4 = lane & 3;

    if (nt < 8 && tid < 64) sbias[tid] = bias[n0 + tid];

    float acc[2][4][4];
    #pragma unroll
    for (int a = 0; a < 2; a++)
        #pragma unroll
        for (int b = 0; b < 4; b++)
            #pragma unroll
            for (int c = 0; c < 4; c++) acc[a][b][c] = 0.f;

    // ---- load helpers (inline) ----
    auto loadA = [&](int st, int kt) {
        #pragma unroll
        for (int j = 0; j < 4; j++) {
            int i = tid + j * 256;
            int r = i >> 3, c8 = i & 7;
            int grow = m0 + r; if (grow >= M) grow = M - 1;
            cp_async16(sA + st * ASZ + r * SA + c8 * 8,
                       g_qbf + (size_t)grow * D + kt * 64 + c8 * 8);
        }
    };
    auto loadB = [&](int st, int kt) {
        #pragma unroll
        for (int j = 0; j < 2; j++) {
            int i = tid + j * 256;
            int r = i >> 3, c8 = i & 7;
            cp_async16(sB + st * BSZ + r * SA + c8 * 8,
                       g_Bbig + (size_t)(n0 + r) * D + kt * 64 + c8 * 8);
        }
    };

    loadA(0, 0); loadB(0, 0); CP_COMMIT();
    loadA(1, 1); loadB(1, 1); CP_COMMIT();

    #pragma unroll 1
    for (int kt = 0; kt < 8; kt++) {
        if (kt < 6) { CP_WAIT(1); } else { CP_WAIT(0); }
        __syncthreads();
        if (kt + 2 < 8) { loadA((kt + 2) % 3, kt + 2); loadB((kt + 2) % 3, kt + 2); CP_COMMIT(); }

        const __nv_bfloat16* ab = sA + (kt % 3) * ASZ;
        const __nv_bfloat16* bb = sB + (kt % 3) * BSZ;
        #pragma unroll
        for (int kk = 0; kk < 64; kk += 16) {
            uint32_t bf[4][2];
            #pragma unroll
            for (int nf = 0; nf < 4; nf++) {
                int n = wn * 32 + nf * 8 + g;
                bf[nf][0] = *(const uint32_t*)(bb + n * SA + kk + t4 * 2);
                bf[nf][1] = *(const uint32_t*)(bb + n * SA + kk + 8 + t4 * 2);
            }
            #pragma unroll
            for (int mf = 0; mf < 2; mf++) {
                int m = wm * 32 + mf * 16;
                uint32_t a0 = *(const uint32_t*)(ab + (m + g) * SA + kk + t4 * 2);
                uint32_t a1 = *(const uint32_t*)(ab + (m + g + 8) * SA + kk + t4 * 2);
                uint32_t a2 = *(const uint32_t*)(ab + (m + g) * SA + kk + 8 + t4 * 2);
                uint32_t a3 = *(const uint32_t*)(ab + (m + g + 8) * SA + kk + 8 + t4 * 2);
                #pragma unroll
                for (int nf = 0; nf < 4; nf++)
                    mma16816(acc[mf][nf], a0, a1, a2, a3, bf[nf][0], bf[nf][1]);
            }
        }
    }

    if (nt < 8) {
        // norm-partial epilogue: sum over this tile's 64 cols of (acc + bias)^2
        #pragma unroll
        for (int mf = 0; mf < 2; mf++) {
            float s0 = 0.f, s1 = 0.f;
            #pragma unroll
            for (int nf = 0; nf < 4; nf++) {
                int c = wn * 32 + nf * 8 + t4 * 2;
                float b0 = sbias[c], b1 = sbias[c + 1];
                float v;
                v = acc[mf][nf][0] + b0; s0 += v * v;
                v = acc[mf][nf][1] + b1; s0 += v * v;
                v = acc[mf][nf][2] + b0; s1 += v * v;
                v = acc[mf][nf][3] + b1; s1 += v * v;
            }
            s0 += __shfl_xor_sync(0xffffffffu, s0, 1);
            s0 += __shfl_xor_sync(0xffffffffu, s0, 2);
            s1 += __shfl_xor_sync(0xffffffffu, s1, 1);
            s1 += __shfl_xor_sync(0xffffffffu, s1, 2);
            if (t4 == 0) {
                int r = wm * 32 + mf * 16 + g;
                snorm[r * 2 + wn] = s0;
                snorm[(r + 8) * 2 + wn] = s1;
            }
        }
        __syncthreads();
        if (tid < 128 && m0 + tid < M)
            g_partial[(size_t)(m0 + tid) * 8 + nt] = snorm[tid * 2] + snorm[tid * 2 + 1];
    } else {
        // cross epilogue: raw dot(q, W^T p_c)
        #pragma unroll
        for (int mf = 0; mf < 2; mf++) {
            int r = wm * 32 + mf * 16 + g;
            #pragma unroll
            for (int nf = 0; nf < 4; nf++) {
                int c = wn * 32 + nf * 8 + t4 * 2;
                if (m0 + r < M) {
                    float2 o; o.x = acc[mf][nf][0]; o.y = acc[mf][nf][1];
                    *(float2*)(g_cross + (size_t)(m0 + r) * NWAY + c) = o;
                }
                if (m0 + r + 8 < M) {
                    float2 o; o.x = acc[mf][nf][2]; o.y = acc[mf][nf][3];
                    *(float2*)(g_cross + (size_t)(m0 + r + 8) * NWAY + c) = o;
                }
            }
        }
    }
}

// ---------------- combine: dist = nq + pcterm - 2*cross ----------------
__global__ void combine_kernel(float* __restrict__ out, int M) {
    __shared__ float snq[4];
    int tid = threadIdx.x;
    int q0 = blockIdx.x * 4;
    if (tid < 4 && q0 + tid < M) {
        float s = 0.f;
        #pragma unroll
        for (int t = 0; t < 8; t++) s += g_partial[(size_t)(q0 + tid) * 8 + t];
        snq[tid] = s;
    }
    __syncthreads();
    int q = q0 + (tid >> 6), c = tid & 63;
    if (q < M)
        out[(size_t)q * NWAY + c] = snq[tid >> 6] + g_pcterm[c]
                                    - 2.f * g_cross[(size_t)q * NWAY + c];
}

// ---------------- launch ----------------
extern "C" void kernel_launch(void* const* d_in, const int* in_sizes, int n_in,
                              void* d_out, int out_size) {
    const float* support = (const float*)d_in[0];
    const float* query   = (const float*)d_in[1];
    const float* W       = (const float*)d_in[2];
    const float* bias    = (const float*)d_in[3];
    int M = in_sizes[1] / D;
    if (M > MAXQ) M = MAXQ;
    float* out = (float*)d_out;

    cudaFuncSetAttribute(main_gemm, cudaFuncAttributeMaxDynamicSharedMemorySize, SM_MAIN);

    int qblocks = (int)(((size_t)M * D + 2047) / 2048);
    prep_kernel<<<qblocks + 256 + NWAY, 256>>>(query, W, support, qblocks, M);
    proto_proj_kernel<<<D / 4, 128>>>(W, bias);
    proto_norm_kernel<<<NWAY, 128>>>(bias);
    r_kernel<<<dim3(4, 32), 256>>>(W);
    main_gemm<<<dim3((M + 127) / 128, 9), 256, SM_MAIN>>>(bias, M);
    combine_kernel<<<(M + 3) / 4, 256>>>(out, M);
}

// round 5
// speedup vs baseline: 1.0469x; 1.0469x over previous
#include <cuda_runtime.h>
#include <cuda_bf16.h>
#include <cstdint>

#define D      512
#define NWAY   64
#define KSHOT  16
#define MAXQ   8192
#define SA     72            // smem K-stride (bf16): 144B rows, LDSM conflict-free
#define ASZ    (128 * SA)    // main A stage elems
#define BSZ    (64 * SA)     // main B stage elems

// ---------------- device scratch ----------------
__device__ float          g_smean[NWAY * D];
__device__ __nv_bfloat16  g_smh[NWAY * D];
__device__ __nv_bfloat16  g_sml[NWAY * D];
__device__ float          g_pfp32[NWAY * D];
__device__ __nv_bfloat16  g_Pbf[NWAY * D];
__device__ float          g_pcterm[NWAY];
__device__ __nv_bfloat16  g_qbf[(size_t)MAXQ * D];
__device__ __nv_bfloat16  g_Bbig[(512 + NWAY) * D];   // rows 0..511 W(hi), 512..575 R
__device__ __nv_bfloat16  g_Wlo[D * D];
__device__ __nv_bfloat16  g_WbfT[D * D];              // WbfT[k, j] = W[j, k]
__device__ float          g_partial[(size_t)MAXQ * 8];
__device__ float          g_cross[(size_t)MAXQ * NWAY];

// ---------------- mma / ldmatrix / cp.async helpers ----------------
__device__ __forceinline__ void mma16816(float* c,
                                         uint32_t a0, uint32_t a1, uint32_t a2, uint32_t a3,
                                         uint32_t b0, uint32_t b1) {
    asm volatile(
        "mma.sync.aligned.m16n8k16.row.col.f32.bf16.bf16.f32 "
        "{%0,%1,%2,%3},{%4,%5,%6,%7},{%8,%9},{%0,%1,%2,%3};\n"
        : "+f"(c[0]), "+f"(c[1]), "+f"(c[2]), "+f"(c[3])
        : "r"(a0), "r"(a1), "r"(a2), "r"(a3), "r"(b0), "r"(b1));
}
__device__ __forceinline__ void ldsm4(uint32_t* r, uint32_t a) {
    asm volatile("ldmatrix.sync.aligned.m8n8.x4.shared.b16 {%0,%1,%2,%3}, [%4];"
                 : "=r"(r[0]), "=r"(r[1]), "=r"(r[2]), "=r"(r[3]) : "r"(a));
}
__device__ __forceinline__ void cp_async16(void* smem, const void* gmem) {
    uint32_t s = (uint32_t)__cvta_generic_to_shared(smem);
    asm volatile("cp.async.cg.shared.global [%0], [%1], 16;\n" :: "r"(s), "l"(gmem));
}
#define CP_COMMIT() asm volatile("cp.async.commit_group;\n")
#define CP_WAIT(n)  asm volatile("cp.async.wait_group %0;\n" :: "n"(n))

// One K=64 slab of a 32x32 warp tile: 2 m-frags x 4 n-frags, ldmatrix-fed.
// B is stored [n][k] row-major in SMEM -> NON-trans ldmatrix yields the
// mma.row.col B fragment directly (k-pair consecutive at fixed n).
__device__ __forceinline__ void tile_step(float acc[2][4][4], uint32_t aA, uint32_t aB,
                                          int aOff0, int aOff1, int bOff0, int bOff1) {
    #pragma unroll
    for (int kk = 0; kk < 64; kk += 16) {
        uint32_t br0[4], br1[4];
        ldsm4(br0, aB + bOff0 + kk * 2);
        ldsm4(br1, aB + bOff1 + kk * 2);
        #pragma unroll
        for (int mf = 0; mf < 2; mf++) {
            uint32_t ar[4];
            ldsm4(ar, aA + (mf ? aOff1 : aOff0) + kk * 2);
            mma16816(acc[mf][0], ar[0], ar[1], ar[2], ar[3], br0[0], br0[1]);
            mma16816(acc[mf][1], ar[0], ar[1], ar[2], ar[3], br0[2], br0[3]);
            mma16816(acc[mf][2], ar[0], ar[1], ar[2], ar[3], br1[0], br1[1]);
            mma16816(acc[mf][3], ar[0], ar[1], ar[2], ar[3], br1[2], br1[3]);
        }
    }
}

// ---------------- prep: Q->bf16, W hi/lo, W^T, means (fp32 + hi/lo) ----------------
__global__ void prep_kernel(const float* __restrict__ q, const float* __restrict__ W,
                            const float* __restrict__ support, int qblocks, int M) {
    int b = blockIdx.x;
    int tid = threadIdx.x;
    if (b < qblocks) {
        size_t total = (size_t)M * D;
        size_t base = (size_t)b * 2048 + tid * 8;
        if (base + 8 <= total) {
            float4 v0 = *(const float4*)(q + base);
            float4 v1 = *(const float4*)(q + base + 4);
            __nv_bfloat162 p0 = __floats2bfloat162_rn(v0.x, v0.y);
            __nv_bfloat162 p1 = __floats2bfloat162_rn(v0.z, v0.w);
            __nv_bfloat162 p2 = __floats2bfloat162_rn(v1.x, v1.y);
            __nv_bfloat162 p3 = __floats2bfloat162_rn(v1.z, v1.w);
            uint4 o;
            o.x = *(uint32_t*)&p0; o.y = *(uint32_t*)&p1;
            o.z = *(uint32_t*)&p2; o.w = *(uint32_t*)&p3;
            *(uint4*)(g_qbf + base) = o;
        } else {
            for (int e = 0; e < 8; e++)
                if (base + e < total) g_qbf[base + e] = __float2bfloat16(q[base + e]);
        }
    } else if (b < qblocks + 256) {
        // W hi/lo convert
        int base = (b - qblocks) * 1024 + tid * 4;
        float4 v = *(const float4*)(W + base);
        __nv_bfloat16 h0 = __float2bfloat16(v.x), h1 = __float2bfloat16(v.y);
        __nv_bfloat16 h2 = __float2bfloat16(v.z), h3 = __float2bfloat16(v.w);
        *(__nv_bfloat162*)(g_Bbig + base)     = __halves2bfloat162(h0, h1);
        *(__nv_bfloat162*)(g_Bbig + base + 2) = __halves2bfloat162(h2, h3);
        *(__nv_bfloat162*)(g_Wlo + base) =
            __floats2bfloat162_rn(v.x - __bfloat162float(h0), v.y - __bfloat162float(h1));
        *(__nv_bfloat162*)(g_Wlo + base + 2) =
            __floats2bfloat162_rn(v.z - __bfloat162float(h2), v.w - __bfloat162float(h3));
    } else if (b < qblocks + 256 + 64) {
        // W transpose: 64x64 tile -> g_WbfT (bf16)
        __shared__ float ts[64][68];
        int t = b - qblocks - 256;
        int r0 = (t >> 3) * 64, c0 = (t & 7) * 64;
        #pragma unroll
        for (int it = 0; it < 4; it++) {
            int r = (tid >> 4) + it * 16;
            float4 v = *(const float4*)(W + (size_t)(r0 + r) * D + c0 + (tid & 15) * 4);
            ts[r][(tid & 15) * 4 + 0] = v.x; ts[r][(tid & 15) * 4 + 1] = v.y;
            ts[r][(tid & 15) * 4 + 2] = v.z; ts[r][(tid & 15) * 4 + 3] = v.w;
        }
        __syncthreads();
        int kk = tid >> 2, jb = (tid & 3) * 16;
        #pragma unroll
        for (int e = 0; e < 16; e += 2) {
            *(__nv_bfloat162*)(g_WbfT + (size_t)(c0 + kk) * D + r0 + jb + e) =
                __floats2bfloat162_rn(ts[jb + e][kk], ts[jb + e + 1][kk]);
        }
    } else {
        // class means fp32 + hi/lo bf16
        int c = b - qblocks - 256 - 64;
        for (int col = tid; col < D; col += blockDim.x) {
            float s = 0.f;
            #pragma unroll
            for (int k = 0; k < KSHOT; k++) s += support[(size_t)(c * KSHOT + k) * D + col];
            s *= (1.f / KSHOT);
            g_smean[c * D + col] = s;
            __nv_bfloat16 h = __float2bfloat16(s);
            g_smh[c * D + col] = h;
            g_sml[c * D + col] = __float2bfloat16(s - __bfloat162float(h));
        }
    }
}

// ---------------- proj: P = smean @ W^T + b  (hi/lo split MMA, fp32 accuracy) ----------------
// grid 4 blocks, each 64(M=classes) x 128(N=j cols), K=512. warps 2(M)x4(N).
#define PA 4608   // 64*SA
#define PB 9216   // 128*SA
#define PROJ_STAGE (2 * PA + 2 * PB)
#define PROJ_SMEM  (2 * PROJ_STAGE * 2)

__global__ __launch_bounds__(256) void proj_kernel(const float* __restrict__ bias) {
    extern __shared__ __nv_bfloat16 sm[];
    int tid = threadIdx.x;
    int nb = blockIdx.x * 128;
    int warp = tid >> 5, lane = tid & 31;
    int wm = warp & 1, wn = warp >> 1;
    int g = lane >> 2, t4 = lane & 3;

    int aOff0 = (((wm * 32 + 0 + (lane & 15)) * SA + (lane >> 4) * 8)) * 2;
    int aOff1 = (((wm * 32 + 16 + (lane & 15)) * SA + (lane >> 4) * 8)) * 2;
    int bOff0 = (((wn * 32 + 0 + (lane & 7) + ((lane >> 4) << 3)) * SA + ((lane >> 3) & 1) * 8)) * 2;
    int bOff1 = (((wn * 32 + 16 + (lane & 7) + ((lane >> 4) << 3)) * SA + ((lane >> 3) & 1) * 8)) * 2;

    auto load = [&](int st, int kt) {
        __nv_bfloat16* base = sm + st * PROJ_STAGE;
        #pragma unroll
        for (int j = 0; j < 2; j++) {
            int i = tid + j * 256, r = i >> 3, c8 = i & 7;
            cp_async16(base + r * SA + c8 * 8, g_smh + (size_t)r * D + kt * 64 + c8 * 8);
            cp_async16(base + PA + r * SA + c8 * 8, g_sml + (size_t)r * D + kt * 64 + c8 * 8);
        }
        #pragma unroll
        for (int j = 0; j < 4; j++) {
            int i = tid + j * 256, r = i >> 3, c8 = i & 7;
            cp_async16(base + 2 * PA + r * SA + c8 * 8,
                       g_Bbig + (size_t)(nb + r) * D + kt * 64 + c8 * 8);
            cp_async16(base + 2 * PA + PB + r * SA + c8 * 8,
                       g_Wlo + (size_t)(nb + r) * D + kt * 64 + c8 * 8);
        }
        CP_COMMIT();
    };

    float acc[2][4][4];
    #pragma unroll
    for (int a = 0; a < 2; a++)
        #pragma unroll
        for (int b2 = 0; b2 < 4; b2++)
            #pragma unroll
            for (int c = 0; c < 4; c++) acc[a][b2][c] = 0.f;

    uint32_t sm0 = (uint32_t)__cvta_generic_to_shared(sm);
    load(0, 0);
    #pragma unroll 1
    for (int kt = 0; kt < 8; kt++) {
        if (kt + 1 < 8) { load((kt + 1) & 1, kt + 1); CP_WAIT(1); } else { CP_WAIT(0); }
        __syncthreads();
        uint32_t st = sm0 + ((kt & 1) * PROJ_STAGE) * 2;
        tile_step(acc, st, st + 2 * PA * 2, aOff0, aOff1, bOff0, bOff1);                 // ah*bh
        tile_step(acc, st, st + (2 * PA + PB) * 2, aOff0, aOff1, bOff0, bOff1);          // ah*bl
        tile_step(acc, st + PA * 2, st + 2 * PA * 2, aOff0, aOff1, bOff0, bOff1);        // al*bh
        __syncthreads();
    }

    #pragma unroll
    for (int mf = 0; mf < 2; mf++) {
        int m = wm * 32 + mf * 16 + g;
        #pragma unroll
        for (int nf = 0; nf < 4; nf++) {
            int c = wn * 32 + nf * 8 + t4 * 2;
            float b0 = bias[nb + c], b1 = bias[nb + c + 1];
            float v00 = acc[mf][nf][0] + b0, v01 = acc[mf][nf][1] + b1;
            float v10 = acc[mf][nf][2] + b0, v11 = acc[mf][nf][3] + b1;
            g_pfp32[m * D + nb + c] = v00;       g_pfp32[m * D + nb + c + 1] = v01;
            g_pfp32[(m + 8) * D + nb + c] = v10; g_pfp32[(m + 8) * D + nb + c + 1] = v11;
            *(__nv_bfloat162*)(g_Pbf + m * D + nb + c)       = __floats2bfloat162_rn(v00, v01);
            *(__nv_bfloat162*)(g_Pbf + (m + 8) * D + nb + c) = __floats2bfloat162_rn(v10, v11);
        }
    }
}

// ---------------- r_gemm: R = Pbf @ W  ->  g_Bbig rows 512..575; block0 also pcterm ----------------
#define R_STAGE (PA + PB)
#define R_SMEM  (2 * R_STAGE * 2)

__global__ __launch_bounds__(256) void r_kernel(const float* __restrict__ bias) {
    extern __shared__ __nv_bfloat16 sm[];
    int tid = threadIdx.x;
    int nb = blockIdx.x * 128;   // k-column tile of R
    int warp = tid >> 5, lane = tid & 31;
    int wm = warp & 1, wn = warp >> 1;
    int g = lane >> 2, t4 = lane & 3;

    // pcterm (block 0): ||p||^2 - 2 b.p  (fp32 exact)
    if (blockIdx.x == 0) {
        int c = tid >> 2, q4 = tid & 3;
        float p = 0.f, db = 0.f;
        for (int j = q4 * 128; j < q4 * 128 + 128; j++) {
            float v = g_pfp32[c * D + j];
            p += v * v;
            db += bias[j] * v;
        }
        p  += __shfl_xor_sync(0xffffffffu, p, 1);
        p  += __shfl_xor_sync(0xffffffffu, p, 2);
        db += __shfl_xor_sync(0xffffffffu, db, 1);
        db += __shfl_xor_sync(0xffffffffu, db, 2);
        if (q4 == 0) g_pcterm[c] = p - 2.f * db;
    }

    int aOff0 = (((wm * 32 + 0 + (lane & 15)) * SA + (lane >> 4) * 8)) * 2;
    int aOff1 = (((wm * 32 + 16 + (lane & 15)) * SA + (lane >> 4) * 8)) * 2;
    int bOff0 = (((wn * 32 + 0 + (lane & 7) + ((lane >> 4) << 3)) * SA + ((lane >> 3) & 1) * 8)) * 2;
    int bOff1 = (((wn * 32 + 16 + (lane & 7) + ((lane >> 4) << 3)) * SA + ((lane >> 3) & 1) * 8)) * 2;

    auto load = [&](int st, int kt) {   // K dim = j
        __nv_bfloat16* base = sm + st * R_STAGE;
        #pragma unroll
        for (int j = 0; j < 2; j++) {
            int i = tid + j * 256, r = i >> 3, c8 = i & 7;
            cp_async16(base + r * SA + c8 * 8, g_Pbf + (size_t)r * D + kt * 64 + c8 * 8);
        }
        #pragma unroll
        for (int j = 0; j < 4; j++) {
            int i = tid + j * 256, r = i >> 3, c8 = i & 7;
            cp_async16(base + PA + r * SA + c8 * 8,
                       g_WbfT + (size_t)(nb + r) * D + kt * 64 + c8 * 8);
        }
        CP_COMMIT();
    };

    float acc[2][4][4];
    #pragma unroll
    for (int a = 0; a < 2; a++)
        #pragma unroll
        for (int b2 = 0; b2 < 4; b2++)
            #pragma unroll
            for (int c = 0; c < 4; c++) acc[a][b2][c] = 0.f;

    uint32_t sm0 = (uint32_t)__cvta_generic_to_shared(sm);
    load(0, 0);
    #pragma unroll 1
    for (int kt = 0; kt < 8; kt++) {
        if (kt + 1 < 8) { load((kt + 1) & 1, kt + 1); CP_WAIT(1); } else { CP_WAIT(0); }
        __syncthreads();
        uint32_t st = sm0 + ((kt & 1) * R_STAGE) * 2;
        tile_step(acc, st, st + PA * 2, aOff0, aOff1, bOff0, bOff1);
        __syncthreads();
    }

    #pragma unroll
    for (int mf = 0; mf < 2; mf++) {
        int m = wm * 32 + mf * 16 + g;
        #pragma unroll
        for (int nf = 0; nf < 4; nf++) {
            int c = wn * 32 + nf * 8 + t4 * 2;
            *(__nv_bfloat162*)(g_Bbig + (size_t)(512 + m) * D + nb + c) =
                __floats2bfloat162_rn(acc[mf][nf][0], acc[mf][nf][1]);
            *(__nv_bfloat162*)(g_Bbig + (size_t)(512 + m + 8) * D + nb + c) =
                __floats2bfloat162_rn(acc[mf][nf][2], acc[mf][nf][3]);
        }
    }
}

// ---------------- main GEMM: C = Qbf @ Bbig^T, LDSM-fed, 3-stage cp.async ----------------
#define SM_BIAS  (3 * (ASZ + BSZ) * 2)
#define SM_NORM  (SM_BIAS + 64 * 4)
#define SM_MAIN  (SM_NORM + 128 * 2 * 4)

__global__ __launch_bounds__(256, 2) void main_gemm(const float* __restrict__ bias, int M) {
    extern __shared__ char smc[];
    __nv_bfloat16* sA = (__nv_bfloat16*)smc;
    __nv_bfloat16* sB = (__nv_bfloat16*)smc + 3 * ASZ;
    float* sbias = (float*)(smc + SM_BIAS);
    float* snorm = (float*)(smc + SM_NORM);

    int tid = threadIdx.x;
    int m0 = blockIdx.x * 128;
    int nt = blockIdx.y;
    int n0 = nt * 64;
    int warp = tid >> 5, lane = tid & 31;
    int wm = warp & 3, wn = warp >> 2;   // 4(M) x 2(N) warps; warp tile 32x32
    int g = lane >> 2, t4 = lane & 3;

    if (nt < 8 && tid < 64) sbias[tid] = bias[n0 + tid];

    int aOff0 = (((wm * 32 + 0 + (lane & 15)) * SA + (lane >> 4) * 8)) * 2;
    int aOff1 = (((wm * 32 + 16 + (lane & 15)) * SA + (lane >> 4) * 8)) * 2;
    int bOff0 = (((wn * 32 + 0 + (lane & 7) + ((lane >> 4) << 3)) * SA + ((lane >> 3) & 1) * 8)) * 2;
    int bOff1 = (((wn * 32 + 16 + (lane & 7) + ((lane >> 4) << 3)) * SA + ((lane >> 3) & 1) * 8)) * 2;

    float acc[2][4][4];
    #pragma unroll
    for (int a = 0; a < 2; a++)
        #pragma unroll
        for (int b2 = 0; b2 < 4; b2++)
            #pragma unroll
            for (int c = 0; c < 4; c++) acc[a][b2][c] = 0.f;

    auto loadA = [&](int st, int kt) {
        #pragma unroll
        for (int j = 0; j < 4; j++) {
            int i = tid + j * 256, r = i >> 3, c8 = i & 7;
            int grow = m0 + r; if (grow >= M) grow = M - 1;
            cp_async16(sA + st * ASZ + r * SA + c8 * 8,
                       g_qbf + (size_t)grow * D + kt * 64 + c8 * 8);
        }
    };
    auto loadB = [&](int st, int kt) {
        #pragma unroll
        for (int j = 0; j < 2; j++) {
            int i = tid + j * 256, r = i >> 3, c8 = i & 7;
            cp_async16(sB + st * BSZ + r * SA + c8 * 8,
                       g_Bbig + (size_t)(n0 + r) * D + kt * 64 + c8 * 8);
        }
    };

    loadA(0, 0); loadB(0, 0); CP_COMMIT();
    loadA(1, 1); loadB(1, 1); CP_COMMIT();

    uint32_t sa0 = (uint32_t)__cvta_generic_to_shared(sA);
    uint32_t sb0 = (uint32_t)__cvta_generic_to_shared(sB);

    #pragma unroll 1
    for (int kt = 0; kt < 8; kt++) {
        if (kt < 6) { CP_WAIT(1); } else { CP_WAIT(0); }
        __syncthreads();
        if (kt + 2 < 8) { loadA((kt + 2) % 3, kt + 2); loadB((kt + 2) % 3, kt + 2); CP_COMMIT(); }
        tile_step(acc, sa0 + ((kt % 3) * ASZ) * 2, sb0 + ((kt % 3) * BSZ) * 2,
                  aOff0, aOff1, bOff0, bOff1);
    }

    if (nt < 8) {
        #pragma unroll
        for (int mf = 0; mf < 2; mf++) {
            float s0 = 0.f, s1 = 0.f;
            #pragma unroll
            for (int nf = 0; nf < 4; nf++) {
                int c = wn * 32 + nf * 8 + t4 * 2;
                float b0 = sbias[c], b1 = sbias[c + 1];
                float v;
                v = acc[mf][nf][0] + b0; s0 += v * v;
                v = acc[mf][nf][1] + b1; s0 += v * v;
                v = acc[mf][nf][2] + b0; s1 += v * v;
                v = acc[mf][nf][3] + b1; s1 += v * v;
            }
            s0 += __shfl_xor_sync(0xffffffffu, s0, 1);
            s0 += __shfl_xor_sync(0xffffffffu, s0, 2);
            s1 += __shfl_xor_sync(0xffffffffu, s1, 1);
            s1 += __shfl_xor_sync(0xffffffffu, s1, 2);
            if (t4 == 0) {
                int r = wm * 32 + mf * 16 + g;
                snorm[r * 2 + wn] = s0;
                snorm[(r + 8) * 2 + wn] = s1;
            }
        }
        __syncthreads();
        if (tid < 128 && m0 + tid < M)
            g_partial[(size_t)(m0 + tid) * 8 + nt] = snorm[tid * 2] + snorm[tid * 2 + 1];
    } else {
        #pragma unroll
        for (int mf = 0; mf < 2; mf++) {
            int r = wm * 32 + mf * 16 + g;
            #pragma unroll
            for (int nf = 0; nf < 4; nf++) {
                int c = wn * 32 + nf * 8 + t4 * 2;
                if (m0 + r < M) {
                    float2 o; o.x = acc[mf][nf][0]; o.y = acc[mf][nf][1];
                    *(float2*)(g_cross + (size_t)(m0 + r) * NWAY + c) = o;
                }
                if (m0 + r + 8 < M) {
                    float2 o; o.x = acc[mf][nf][2]; o.y = acc[mf][nf][3];
                    *(float2*)(g_cross + (size_t)(m0 + r + 8) * NWAY + c) = o;
                }
            }
        }
    }
}

// ---------------- combine: dist = nq + pcterm - 2*cross ----------------
__global__ void combine_kernel(float* __restrict__ out, int M) {
    __shared__ float snq[4];
    int tid = threadIdx.x;
    int q0 = blockIdx.x * 4;
    if (tid < 4 && q0 + tid < M) {
        float s = 0.f;
        #pragma unroll
        for (int t = 0; t < 8; t++) s += g_partial[(size_t)(q0 + tid) * 8 + t];
        snq[tid] = s;
    }
    __syncthreads();
    int q = q0 + (tid >> 6), c = tid & 63;
    if (q < M)
        out[(size_t)q * NWAY + c] = snq[tid >> 6] + g_pcterm[c]
                                    - 2.f * g_cross[(size_t)q * NWAY + c];
}

// ---------------- launch ----------------
extern "C" void kernel_launch(void* const* d_in, const int* in_sizes, int n_in,
                              void* d_out, int out_size) {
    const float* support = (const float*)d_in[0];
    const float* query   = (const float*)d_in[1];
    const float* W       = (const float*)d_in[2];
    const float* bias    = (const float*)d_in[3];
    int M = in_sizes[1] / D;
    if (M > MAXQ) M = MAXQ;
    float* out = (float*)d_out;

    cudaFuncSetAttribute(proj_kernel, cudaFuncAttributeMaxDynamicSharedMemorySize, PROJ_SMEM);
    cudaFuncSetAttribute(r_kernel,    cudaFuncAttributeMaxDynamicSharedMemorySize, R_SMEM);
    cudaFuncSetAttribute(main_gemm,   cudaFuncAttributeMaxDynamicSharedMemorySize, SM_MAIN);

    int qblocks = (int)(((size_t)M * D + 2047) / 2048);
    prep_kernel<<<qblocks + 256 + 64 + NWAY, 256>>>(query, W, support, qblocks, M);
    proj_kernel<<<4, 256, PROJ_SMEM>>>(bias);
    r_kernel<<<4, 256, R_SMEM>>>(bias);
    main_gemm<<<dim3((M + 127) / 128, 9), 256, SM_MAIN>>>(bias, M);
    combine_kernel<<<(M + 3) / 4, 256>>>(out, M);
}

// round 7
// speedup vs baseline: 1.2647x; 1.2080x over previous
#include <cuda_runtime.h>
#include <cuda_bf16.h>
#include <cstdint>

#define D      512
#define NWAY   64
#define KSHOT  16
#define MAXQ   8192
#define SA     72            // smem K-stride (bf16): 144B rows, LDSM conflict-free
#define ASZ    (128 * SA)
#define BSZ    (64 * SA)
#define PA     (64 * SA)
#define PB     (128 * SA)

// ---------------- device scratch ----------------
__device__ float          g_smean[NWAY * D];
__device__ __nv_bfloat16  g_smeanbf[NWAY * D];
__device__ float          g_u[D];                     // W^T b
__device__ float          g_bb;                       // ||b||^2
__device__ float          g_pcpart[4 * NWAY];         // per-R-block pcterm partials
__device__ __nv_bfloat16  g_qbf[(size_t)MAXQ * D];
__device__ __nv_bfloat16  g_Bbig[(512 + NWAY) * D];   // rows 0..511 W(bf16), 512..575 R
__device__ __nv_bfloat16  g_WbfT[D * D];              // WbfT[k, j] = W[j, k]
__device__ __nv_bfloat16  g_Gbf[D * D];               // G = W^T W (bf16)
__device__ float          g_partial[(size_t)MAXQ * 8];
__device__ float          g_cross[(size_t)MAXQ * NWAY];

// ---------------- mma / ldmatrix / cp.async helpers ----------------
__device__ __forceinline__ void mma16816(float* c,
                                         uint32_t a0, uint32_t a1, uint32_t a2, uint32_t a3,
                                         uint32_t b0, uint32_t b1) {
    asm volatile(
        "mma.sync.aligned.m16n8k16.row.col.f32.bf16.bf16.f32 "
        "{%0,%1,%2,%3},{%4,%5,%6,%7},{%8,%9},{%0,%1,%2,%3};\n"
        : "+f"(c[0]), "+f"(c[1]), "+f"(c[2]), "+f"(c[3])
        : "r"(a0), "r"(a1), "r"(a2), "r"(a3), "r"(b0), "r"(b1));
}
__device__ __forceinline__ void ldsm4(uint32_t* r, uint32_t a) {
    asm volatile("ldmatrix.sync.aligned.m8n8.x4.shared.b16 {%0,%1,%2,%3}, [%4];"
                 : "=r"(r[0]), "=r"(r[1]), "=r"(r[2]), "=r"(r[3]) : "r"(a));
}
__device__ __forceinline__ void cp_async16(void* smem, const void* gmem) {
    uint32_t s = (uint32_t)__cvta_generic_to_shared(smem);
    asm volatile("cp.async.cg.shared.global [%0], [%1], 16;\n" :: "r"(s), "l"(gmem));
}
#define CP_COMMIT() asm volatile("cp.async.commit_group;\n")
#define CP_WAIT(n)  asm volatile("cp.async.wait_group %0;\n" :: "n"(n))

// One K=64 slab of a 32x32 warp tile: 2 m-frags x 4 n-frags, ldmatrix-fed.
__device__ __forceinline__ void tile_step(float acc[2][4][4], uint32_t aA, uint32_t aB,
                                          int aOff0, int aOff1, int bOff0, int bOff1) {
    #pragma unroll
    for (int kk = 0; kk < 64; kk += 16) {
        uint32_t br0[4], br1[4];
        ldsm4(br0, aB + bOff0 + kk * 2);
        ldsm4(br1, aB + bOff1 + kk * 2);
        #pragma unroll
        for (int mf = 0; mf < 2; mf++) {
            uint32_t ar[4];
            ldsm4(ar, aA + (mf ? aOff1 : aOff0) + kk * 2);
            mma16816(acc[mf][0], ar[0], ar[1], ar[2], ar[3], br0[0], br0[1]);
            mma16816(acc[mf][1], ar[0], ar[1], ar[2], ar[3], br0[2], br0[3]);
            mma16816(acc[mf][2], ar[0], ar[1], ar[2], ar[3], br1[0], br1[1]);
            mma16816(acc[mf][3], ar[0], ar[1], ar[2], ar[3], br1[2], br1[3]);
        }
    }
}

// ---------------- prep (256 threads/block): Q->bf16, W->bf16, W^T, smean, u, ||b||^2 ----------------
__global__ void prep_kernel(const float* __restrict__ q, const float* __restrict__ W,
                            const float* __restrict__ support, const float* __restrict__ bias,
                            int qblocks, int M) {
    int b = blockIdx.x;
    int tid = threadIdx.x;   // 0..255
    if (b < qblocks) {
        size_t total = (size_t)M * D;
        size_t base = (size_t)b * 2048 + tid * 8;
        if (base + 8 <= total) {
            float4 v0 = *(const float4*)(q + base);
            float4 v1 = *(const float4*)(q + base + 4);
            __nv_bfloat162 p0 = __floats2bfloat162_rn(v0.x, v0.y);
            __nv_bfloat162 p1 = __floats2bfloat162_rn(v0.z, v0.w);
            __nv_bfloat162 p2 = __floats2bfloat162_rn(v1.x, v1.y);
            __nv_bfloat162 p3 = __floats2bfloat162_rn(v1.z, v1.w);
            uint4 o;
            o.x = *(uint32_t*)&p0; o.y = *(uint32_t*)&p1;
            o.z = *(uint32_t*)&p2; o.w = *(uint32_t*)&p3;
            *(uint4*)(g_qbf + base) = o;
        } else {
            for (int e = 0; e < 8; e++)
                if (base + e < total) g_qbf[base + e] = __float2bfloat16(q[base + e]);
        }
    } else if (b < qblocks + 256) {
        // W -> bf16 into g_Bbig rows 0..511 (256 thr x 4 = 1024 elems/block)
        int base = (b - qblocks) * 1024 + tid * 4;
        float4 v = *(const float4*)(W + base);
        *(__nv_bfloat162*)(g_Bbig + base)     = __floats2bfloat162_rn(v.x, v.y);
        *(__nv_bfloat162*)(g_Bbig + base + 2) = __floats2bfloat162_rn(v.z, v.w);
    } else if (b < qblocks + 256 + 64) {
        // W transpose: 64x64 tile -> g_WbfT (bf16); written for 256 threads
        __shared__ float ts[64][68];
        int t = b - qblocks - 256;
        int r0 = (t >> 3) * 64, c0 = (t & 7) * 64;
        #pragma unroll
        for (int it = 0; it < 4; it++) {
            int r = (tid >> 4) + it * 16;
            float4 v = *(const float4*)(W + (size_t)(r0 + r) * D + c0 + (tid & 15) * 4);
            ts[r][(tid & 15) * 4 + 0] = v.x; ts[r][(tid & 15) * 4 + 1] = v.y;
            ts[r][(tid & 15) * 4 + 2] = v.z; ts[r][(tid & 15) * 4 + 3] = v.w;
        }
        __syncthreads();
        int kk = tid >> 2, jb = (tid & 3) * 16;
        #pragma unroll
        for (int e = 0; e < 16; e += 2) {
            *(__nv_bfloat162*)(g_WbfT + (size_t)(c0 + kk) * D + r0 + jb + e) =
                __floats2bfloat162_rn(ts[jb + e][kk], ts[jb + e + 1][kk]);
        }
    } else if (b < qblocks + 256 + 64 + 64) {
        // class means fp32 + bf16 (stride blockDim.x -> thread-count agnostic)
        int c = b - qblocks - 256 - 64;
        for (int col = tid; col < D; col += blockDim.x) {
            float s = 0.f;
            #pragma unroll
            for (int k = 0; k < KSHOT; k++) s += support[(size_t)(c * KSHOT + k) * D + col];
            s *= (1.f / KSHOT);
            g_smean[c * D + col] = s;
            g_smeanbf[c * D + col] = __float2bfloat16(s);
        }
    } else if (b < qblocks + 256 + 64 + 64 + 2) {
        // u = W^T b : 256 k-cols per block, 2 blocks
        int k = (b - qblocks - 256 - 64 - 64) * 256 + tid;
        float acc = 0.f;
        #pragma unroll 8
        for (int j = 0; j < D; j++) acc += bias[j] * W[(size_t)j * D + k];
        g_u[k] = acc;
    } else {
        // ||b||^2 (256 threads, stride 256, 8-warp combine)
        float s = 0.f;
        for (int j = tid; j < D; j += 256) { float v = bias[j]; s += v * v; }
        #pragma unroll
        for (int o = 16; o > 0; o >>= 1) s += __shfl_xor_sync(0xffffffffu, s, o);
        __shared__ float red[8];
        if ((tid & 31) == 0) red[tid >> 5] = s;
        __syncthreads();
        if (tid == 0) {
            float t2 = 0.f;
            #pragma unroll
            for (int w = 0; w < 8; w++) t2 += red[w];
            g_bb = t2;
        }
    }
}

// ---------------- G = W^T W  (both operands = g_WbfT), 128x64 tiles ----------------
#define SM_G (3 * (ASZ + BSZ) * 2)
__global__ __launch_bounds__(256, 2) void g_gemm(int dummy) {
    extern __shared__ char smc[];
    __nv_bfloat16* sA = (__nv_bfloat16*)smc;
    __nv_bfloat16* sB = (__nv_bfloat16*)smc + 3 * ASZ;
    int tid = threadIdx.x;
    int m0 = blockIdx.x * 128, n0 = blockIdx.y * 64;
    int warp = tid >> 5, lane = tid & 31;
    int wm = warp & 3, wn = warp >> 2;
    int g = lane >> 2, t4 = lane & 3;

    int aOff0 = (((wm * 32 + 0 + (lane & 15)) * SA + (lane >> 4) * 8)) * 2;
    int aOff1 = (((wm * 32 + 16 + (lane & 15)) * SA + (lane >> 4) * 8)) * 2;
    int bOff0 = (((wn * 32 + 0 + (lane & 7) + ((lane >> 4) << 3)) * SA + ((lane >> 3) & 1) * 8)) * 2;
    int bOff1 = (((wn * 32 + 16 + (lane & 7) + ((lane >> 4) << 3)) * SA + ((lane >> 3) & 1) * 8)) * 2;

    float acc[2][4][4];
    #pragma unroll
    for (int a = 0; a < 2; a++)
        #pragma unroll
        for (int b2 = 0; b2 < 4; b2++)
            #pragma unroll
            for (int c = 0; c < 4; c++) acc[a][b2][c] = 0.f;

    auto loadA = [&](int st, int kt) {
        #pragma unroll
        for (int j = 0; j < 4; j++) {
            int i = tid + j * 256, r = i >> 3, c8 = i & 7;
            cp_async16(sA + st * ASZ + r * SA + c8 * 8,
                       g_WbfT + (size_t)(m0 + r) * D + kt * 64 + c8 * 8);
        }
    };
    auto loadB = [&](int st, int kt) {
        #pragma unroll
        for (int j = 0; j < 2; j++) {
            int i = tid + j * 256, r = i >> 3, c8 = i & 7;
            cp_async16(sB + st * BSZ + r * SA + c8 * 8,
                       g_WbfT + (size_t)(n0 + r) * D + kt * 64 + c8 * 8);
        }
    };

    loadA(0, 0); loadB(0, 0); CP_COMMIT();
    loadA(1, 1); loadB(1, 1); CP_COMMIT();
    uint32_t sa0 = (uint32_t)__cvta_generic_to_shared(sA);
    uint32_t sb0 = (uint32_t)__cvta_generic_to_shared(sB);

    #pragma unroll 1
    for (int kt = 0; kt < 8; kt++) {
        if (kt < 6) { CP_WAIT(1); } else { CP_WAIT(0); }
        __syncthreads();
        if (kt + 2 < 8) { loadA((kt + 2) % 3, kt + 2); loadB((kt + 2) % 3, kt + 2); CP_COMMIT(); }
        tile_step(acc, sa0 + ((kt % 3) * ASZ) * 2, sb0 + ((kt % 3) * BSZ) * 2,
                  aOff0, aOff1, bOff0, bOff1);
    }

    #pragma unroll
    for (int mf = 0; mf < 2; mf++) {
        int m = m0 + wm * 32 + mf * 16 + g;
        #pragma unroll
        for (int nf = 0; nf < 4; nf++) {
            int c = n0 + wn * 32 + nf * 8 + t4 * 2;
            *(__nv_bfloat162*)(g_Gbf + (size_t)m * D + c) =
                __floats2bfloat162_rn(acc[mf][nf][0], acc[mf][nf][1]);
            *(__nv_bfloat162*)(g_Gbf + (size_t)(m + 8) * D + c) =
                __floats2bfloat162_rn(acc[mf][nf][2], acc[mf][nf][3]);
        }
    }
}

// ---------------- R = smean_bf @ G + u  -> g_Bbig rows 512..575; pcterm partials ----------------
#define SM_R (2 * (PA + PB) * 2)
__global__ __launch_bounds__(256) void r_gemm(int dummy) {
    extern __shared__ __nv_bfloat16 sm[];
    __shared__ float spart[64][4];
    int tid = threadIdx.x;
    int n0 = blockIdx.x * 128;
    int warp = tid >> 5, lane = tid & 31;
    int wm = warp & 1, wn = warp >> 1;
    int g = lane >> 2, t4 = lane & 3;

    int aOff0 = (((wm * 32 + 0 + (lane & 15)) * SA + (lane >> 4) * 8)) * 2;
    int aOff1 = (((wm * 32 + 16 + (lane & 15)) * SA + (lane >> 4) * 8)) * 2;
    int bOff0 = (((wn * 32 + 0 + (lane & 7) + ((lane >> 4) << 3)) * SA + ((lane >> 3) & 1) * 8)) * 2;
    int bOff1 = (((wn * 32 + 16 + (lane & 7) + ((lane >> 4) << 3)) * SA + ((lane >> 3) & 1) * 8)) * 2;

    auto load = [&](int st, int kt) {
        __nv_bfloat16* base = sm + st * (PA + PB);
        #pragma unroll
        for (int j = 0; j < 2; j++) {
            int i = tid + j * 256, r = i >> 3, c8 = i & 7;
            cp_async16(base + r * SA + c8 * 8, g_smeanbf + (size_t)r * D + kt * 64 + c8 * 8);
        }
        #pragma unroll
        for (int j = 0; j < 4; j++) {
            int i = tid + j * 256, r = i >> 3, c8 = i & 7;
            cp_async16(base + PA + r * SA + c8 * 8,
                       g_Gbf + (size_t)(n0 + r) * D + kt * 64 + c8 * 8);
        }
        CP_COMMIT();
    };

    float acc[2][4][4];
    #pragma unroll
    for (int a = 0; a < 2; a++)
        #pragma unroll
        for (int b2 = 0; b2 < 4; b2++)
            #pragma unroll
            for (int c = 0; c < 4; c++) acc[a][b2][c] = 0.f;

    uint32_t sm0 = (uint32_t)__cvta_generic_to_shared(sm);
    load(0, 0);
    #pragma unroll 1
    for (int kt = 0; kt < 8; kt++) {
        if (kt + 1 < 8) { load((kt + 1) & 1, kt + 1); CP_WAIT(1); } else { CP_WAIT(0); }
        __syncthreads();
        uint32_t st = sm0 + ((kt & 1) * (PA + PB)) * 2;
        tile_step(acc, st, st + PA * 2, aOff0, aOff1, bOff0, bOff1);
        __syncthreads();
    }

    // epilogue: R = acc + u  (store bf16); pcterm partial = sum_cols s * acc
    #pragma unroll
    for (int mf = 0; mf < 2; mf++) {
        int m = wm * 32 + mf * 16 + g;    // class row 0..63
        float s0 = 0.f, s1 = 0.f;
        #pragma unroll
        for (int nf = 0; nf < 4; nf++) {
            int c = n0 + wn * 32 + nf * 8 + t4 * 2;
            float u0 = g_u[c], u1 = g_u[c + 1];
            float v00 = acc[mf][nf][0], v01 = acc[mf][nf][1];
            float v10 = acc[mf][nf][2], v11 = acc[mf][nf][3];
            s0 += g_smean[m * D + c] * v00 + g_smean[m * D + c + 1] * v01;
            s1 += g_smean[(m + 8) * D + c] * v10 + g_smean[(m + 8) * D + c + 1] * v11;
            *(__nv_bfloat162*)(g_Bbig + (size_t)(512 + m) * D + c) =
                __floats2bfloat162_rn(v00 + u0, v01 + u1);
            *(__nv_bfloat162*)(g_Bbig + (size_t)(512 + m + 8) * D + c) =
                __floats2bfloat162_rn(v10 + u0, v11 + u1);
        }
        s0 += __shfl_xor_sync(0xffffffffu, s0, 1);
        s0 += __shfl_xor_sync(0xffffffffu, s0, 2);
        s1 += __shfl_xor_sync(0xffffffffu, s1, 1);
        s1 += __shfl_xor_sync(0xffffffffu, s1, 2);
        if (t4 == 0) { spart[m][wn] = s0; spart[m + 8][wn] = s1; }
    }
    __syncthreads();
    if (tid < 64)
        g_pcpart[blockIdx.x * 64 + tid] =
            spart[tid][0] + spart[tid][1] + spart[tid][2] + spart[tid][3];
}

// ---------------- main GEMM: C = Qbf @ Bbig^T, LDSM-fed, 3-stage cp.async ----------------
#define SM_BIAS  (3 * (ASZ + BSZ) * 2)
#define SM_NORM  (SM_BIAS + 64 * 4)
#define SM_MAIN  (SM_NORM + 128 * 2 * 4)

__global__ __launch_bounds__(256, 2) void main_gemm(const float* __restrict__ bias, int M) {
    extern __shared__ char smc[];
    __nv_bfloat16* sA = (__nv_bfloat16*)smc;
    __nv_bfloat16* sB = (__nv_bfloat16*)smc + 3 * ASZ;
    float* sbias = (float*)(smc + SM_BIAS);
    float* snorm = (float*)(smc + SM_NORM);

    int tid = threadIdx.x;
    int m0 = blockIdx.x * 128;
    int nt = blockIdx.y;
    int n0 = nt * 64;
    int warp = tid >> 5, lane = tid & 31;
    int wm = warp & 3, wn = warp >> 2;
    int g = lane >> 2, t4 = lane & 3;

    if (nt < 8 && tid < 64) sbias[tid] = bias[n0 + tid];

    int aOff0 = (((wm * 32 + 0 + (lane & 15)) * SA + (lane >> 4) * 8)) * 2;
    int aOff1 = (((wm * 32 + 16 + (lane & 15)) * SA + (lane >> 4) * 8)) * 2;
    int bOff0 = (((wn * 32 + 0 + (lane & 7) + ((lane >> 4) << 3)) * SA + ((lane >> 3) & 1) * 8)) * 2;
    int bOff1 = (((wn * 32 + 16 + (lane & 7) + ((lane >> 4) << 3)) * SA + ((lane >> 3) & 1) * 8)) * 2;

    float acc[2][4][4];
    #pragma unroll
    for (int a = 0; a < 2; a++)
        #pragma unroll
        for (int b2 = 0; b2 < 4; b2++)
            #pragma unroll
            for (int c = 0; c < 4; c++) acc[a][b2][c] = 0.f;

    auto loadA = [&](int st, int kt) {
        #pragma unroll
        for (int j = 0; j < 4; j++) {
            int i = tid + j * 256, r = i >> 3, c8 = i & 7;
            int grow = m0 + r; if (grow >= M) grow = M - 1;
            cp_async16(sA + st * ASZ + r * SA + c8 * 8,
                       g_qbf + (size_t)grow * D + kt * 64 + c8 * 8);
        }
    };
    auto loadB = [&](int st, int kt) {
        #pragma unroll
        for (int j = 0; j < 2; j++) {
            int i = tid + j * 256, r = i >> 3, c8 = i & 7;
            cp_async16(sB + st * BSZ + r * SA + c8 * 8,
                       g_Bbig + (size_t)(n0 + r) * D + kt * 64 + c8 * 8);
        }
    };

    loadA(0, 0); loadB(0, 0); CP_COMMIT();
    loadA(1, 1); loadB(1, 1); CP_COMMIT();

    uint32_t sa0 = (uint32_t)__cvta_generic_to_shared(sA);
    uint32_t sb0 = (uint32_t)__cvta_generic_to_shared(sB);

    #pragma unroll 1
    for (int kt = 0; kt < 8; kt++) {
        if (kt < 6) { CP_WAIT(1); } else { CP_WAIT(0); }
        __syncthreads();
        if (kt + 2 < 8) { loadA((kt + 2) % 3, kt + 2); loadB((kt + 2) % 3, kt + 2); CP_COMMIT(); }
        tile_step(acc, sa0 + ((kt % 3) * ASZ) * 2, sb0 + ((kt % 3) * BSZ) * 2,
                  aOff0, aOff1, bOff0, bOff1);
    }

    if (nt < 8) {
        #pragma unroll
        for (int mf = 0; mf < 2; mf++) {
            float s0 = 0.f, s1 = 0.f;
            #pragma unroll
            for (int nf = 0; nf < 4; nf++) {
                int c = wn * 32 + nf * 8 + t4 * 2;
                float b0 = sbias[c], b1 = sbias[c + 1];
                float v;
                v = acc[mf][nf][0] + b0; s0 += v * v;
                v = acc[mf][nf][1] + b1; s0 += v * v;
                v = acc[mf][nf][2] + b0; s1 += v * v;
                v = acc[mf][nf][3] + b1; s1 += v * v;
            }
            s0 += __shfl_xor_sync(0xffffffffu, s0, 1);
            s0 += __shfl_xor_sync(0xffffffffu, s0, 2);
            s1 += __shfl_xor_sync(0xffffffffu, s1, 1);
            s1 += __shfl_xor_sync(0xffffffffu, s1, 2);
            if (t4 == 0) {
                int r = wm * 32 + mf * 16 + g;
                snorm[r * 2 + wn] = s0;
                snorm[(r + 8) * 2 + wn] = s1;
            }
        }
        __syncthreads();
        if (tid < 128 && m0 + tid < M)
            g_partial[(size_t)(m0 + tid) * 8 + nt] = snorm[tid * 2] + snorm[tid * 2 + 1];
    } else {
        #pragma unroll
        for (int mf = 0; mf < 2; mf++) {
            int r = wm * 32 + mf * 16 + g;
            #pragma unroll
            for (int nf = 0; nf < 4; nf++) {
                int c = wn * 32 + nf * 8 + t4 * 2;
                if (m0 + r < M) {
                    float2 o; o.x = acc[mf][nf][0]; o.y = acc[mf][nf][1];
                    *(float2*)(g_cross + (size_t)(m0 + r) * NWAY + c) = o;
                }
                if (m0 + r + 8 < M) {
                    float2 o; o.x = acc[mf][nf][2]; o.y = acc[mf][nf][3];
                    *(float2*)(g_cross + (size_t)(m0 + r + 8) * NWAY + c) = o;
                }
            }
        }
    }
}

// ---------------- combine: dist = nq + (sum pcpart - ||b||^2) - 2*cross ----------------
__global__ void combine_kernel(float* __restrict__ out, int M) {
    __shared__ float snq[4];
    int tid = threadIdx.x;
    int q0 = blockIdx.x * 4;
    if (tid < 4 && q0 + tid < M) {
        float s = 0.f;
        #pragma unroll
        for (int t = 0; t < 8; t++) s += g_partial[(size_t)(q0 + tid) * 8 + t];
        snq[tid] = s;
    }
    __syncthreads();
    int q = q0 + (tid >> 6), c = tid & 63;
    if (q < M) {
        float pc = g_pcpart[c] + g_pcpart[64 + c] + g_pcpart[128 + c] + g_pcpart[192 + c] - g_bb;
        out[(size_t)q * NWAY + c] = snq[tid >> 6] + pc
                                    - 2.f * g_cross[(size_t)q * NWAY + c];
    }
}

// ---------------- launch ----------------
extern "C" void kernel_launch(void* const* d_in, const int* in_sizes, int n_in,
                              void* d_out, int out_size) {
    const float* support = (const float*)d_in[0];
    const float* query   = (const float*)d_in[1];
    const float* W       = (const float*)d_in[2];
    const float* bias    = (const float*)d_in[3];
    int M = in_sizes[1] / D;
    if (M > MAXQ) M = MAXQ;
    float* out = (float*)d_out;

    cudaFuncSetAttribute(g_gemm,    cudaFuncAttributeMaxDynamicSharedMemorySize, SM_G);
    cudaFuncSetAttribute(r_gemm,    cudaFuncAttributeMaxDynamicSharedMemorySize, SM_R);
    cudaFuncSetAttribute(main_gemm, cudaFuncAttributeMaxDynamicSharedMemorySize, SM_MAIN);

    int qblocks = (int)(((size_t)M * D + 2047) / 2048);
    prep_kernel<<<qblocks + 256 + 64 + 64 + 2 + 1, 256>>>(query, W, support, bias, qblocks, M);
    g_gemm<<<dim3(4, 8), 256, SM_G>>>(0);
    r_gemm<<<4, 256, SM_R>>>(0);
    main_gemm<<<dim3((M + 127) / 128, 9), 256, SM_MAIN>>>(bias, M);
    combine_kernel<<<(M + 3) / 4, 256>>>(out, M);
}

// round 8
// speedup vs baseline: 1.5905x; 1.2576x over previous
#include <cuda_runtime.h>
#include <cuda_bf16.h>
#include <cstdint>

#define D      512
#define NWAY   64
#define KSHOT  16
#define MAXQ   8192
#define SA     72            // smem K-stride (bf16): 144B rows, LDSM conflict-free
#define ASZ    (128 * SA)
#define BSZ    (64 * SA)
#define PA     (64 * SA)
#define PB     (128 * SA)

// ---------------- device scratch ----------------
__device__ float          g_smean[NWAY * D];
__device__ __nv_bfloat16  g_smeanbf[NWAY * D];
__device__ float          g_u[D];                     // W^T b
__device__ float          g_bb;                       // ||b||^2
__device__ float          g_pcterm[NWAY];
__device__ __nv_bfloat16  g_qbf[(size_t)MAXQ * D];
__device__ __nv_bfloat16  g_Bbig[(512 + NWAY) * D];   // rows 0..511 W(bf16), 512..575 R
__device__ __nv_bfloat16  g_WbfT[D * D];              // WbfT[k, j] = W[j, k]
__device__ __nv_bfloat16  g_Gbf[D * D];               // G = W^T W (bf16)
__device__ float          g_Gpart[4 * D * D];         // split-K G partials (fp32)
__device__ float          g_Rpart[2 * NWAY * D];      // split-K R partials (fp32)
__device__ float          g_partial[(size_t)MAXQ * 8];
__device__ float          g_cross[(size_t)MAXQ * NWAY];

// ---------------- mma / ldmatrix / cp.async helpers ----------------
__device__ __forceinline__ void mma16816(float* c,
                                         uint32_t a0, uint32_t a1, uint32_t a2, uint32_t a3,
                                         uint32_t b0, uint32_t b1) {
    asm volatile(
        "mma.sync.aligned.m16n8k16.row.col.f32.bf16.bf16.f32 "
        "{%0,%1,%2,%3},{%4,%5,%6,%7},{%8,%9},{%0,%1,%2,%3};\n"
        : "+f"(c[0]), "+f"(c[1]), "+f"(c[2]), "+f"(c[3])
        : "r"(a0), "r"(a1), "r"(a2), "r"(a3), "r"(b0), "r"(b1));
}
__device__ __forceinline__ void ldsm4(uint32_t* r, uint32_t a) {
    asm volatile("ldmatrix.sync.aligned.m8n8.x4.shared.b16 {%0,%1,%2,%3}, [%4];"
                 : "=r"(r[0]), "=r"(r[1]), "=r"(r[2]), "=r"(r[3]) : "r"(a));
}
__device__ __forceinline__ void cp_async16(void* smem, const void* gmem) {
    uint32_t s = (uint32_t)__cvta_generic_to_shared(smem);
    asm volatile("cp.async.cg.shared.global [%0], [%1], 16;\n" :: "r"(s), "l"(gmem));
}
#define CP_COMMIT() asm volatile("cp.async.commit_group;\n")
#define CP_WAIT(n)  asm volatile("cp.async.wait_group %0;\n" :: "n"(n))

// One K=64 slab of a 32x32 warp tile: 2 m-frags x 4 n-frags, ldmatrix-fed.
__device__ __forceinline__ void tile_step(float acc[2][4][4], uint32_t aA, uint32_t aB,
                                          int aOff0, int aOff1, int bOff0, int bOff1) {
    #pragma unroll
    for (int kk = 0; kk < 64; kk += 16) {
        uint32_t br0[4], br1[4];
        ldsm4(br0, aB + bOff0 + kk * 2);
        ldsm4(br1, aB + bOff1 + kk * 2);
        #pragma unroll
        for (int mf = 0; mf < 2; mf++) {
            uint32_t ar[4];
            ldsm4(ar, aA + (mf ? aOff1 : aOff0) + kk * 2);
            mma16816(acc[mf][0], ar[0], ar[1], ar[2], ar[3], br0[0], br0[1]);
            mma16816(acc[mf][1], ar[0], ar[1], ar[2], ar[3], br0[2], br0[3]);
            mma16816(acc[mf][2], ar[0], ar[1], ar[2], ar[3], br1[0], br1[1]);
            mma16816(acc[mf][3], ar[0], ar[1], ar[2], ar[3], br1[2], br1[3]);
        }
    }
}

// ---------------- prep (256 thr): Q->bf16, W->bf16, W^T, smean, u, ||b||^2 ----------------
__global__ void prep_kernel(const float* __restrict__ q, const float* __restrict__ W,
                            const float* __restrict__ support, const float* __restrict__ bias,
                            int qblocks, int M) {
    int b = blockIdx.x;
    int tid = threadIdx.x;   // 0..255
    if (b < qblocks) {
        size_t total = (size_t)M * D;
        size_t base = (size_t)b * 2048 + tid * 8;
        if (base + 8 <= total) {
            float4 v0 = *(const float4*)(q + base);
            float4 v1 = *(const float4*)(q + base + 4);
            __nv_bfloat162 p0 = __floats2bfloat162_rn(v0.x, v0.y);
            __nv_bfloat162 p1 = __floats2bfloat162_rn(v0.z, v0.w);
            __nv_bfloat162 p2 = __floats2bfloat162_rn(v1.x, v1.y);
            __nv_bfloat162 p3 = __floats2bfloat162_rn(v1.z, v1.w);
            uint4 o;
            o.x = *(uint32_t*)&p0; o.y = *(uint32_t*)&p1;
            o.z = *(uint32_t*)&p2; o.w = *(uint32_t*)&p3;
            *(uint4*)(g_qbf + base) = o;
        } else {
            for (int e = 0; e < 8; e++)
                if (base + e < total) g_qbf[base + e] = __float2bfloat16(q[base + e]);
        }
    } else if (b < qblocks + 256) {
        int base = (b - qblocks) * 1024 + tid * 4;
        float4 v = *(const float4*)(W + base);
        *(__nv_bfloat162*)(g_Bbig + base)     = __floats2bfloat162_rn(v.x, v.y);
        *(__nv_bfloat162*)(g_Bbig + base + 2) = __floats2bfloat162_rn(v.z, v.w);
    } else if (b < qblocks + 256 + 64) {
        // W transpose 64x64 -> g_WbfT
        __shared__ float ts[64][68];
        int t = b - qblocks - 256;
        int r0 = (t >> 3) * 64, c0 = (t & 7) * 64;
        #pragma unroll
        for (int it = 0; it < 4; it++) {
            int r = (tid >> 4) + it * 16;
            float4 v = *(const float4*)(W + (size_t)(r0 + r) * D + c0 + (tid & 15) * 4);
            ts[r][(tid & 15) * 4 + 0] = v.x; ts[r][(tid & 15) * 4 + 1] = v.y;
            ts[r][(tid & 15) * 4 + 2] = v.z; ts[r][(tid & 15) * 4 + 3] = v.w;
        }
        __syncthreads();
        int kk = tid >> 2, jb = (tid & 3) * 16;
        #pragma unroll
        for (int e = 0; e < 16; e += 2) {
            *(__nv_bfloat162*)(g_WbfT + (size_t)(c0 + kk) * D + r0 + jb + e) =
                __floats2bfloat162_rn(ts[jb + e][kk], ts[jb + e + 1][kk]);
        }
    } else if (b < qblocks + 256 + 64 + 64) {
        int c = b - qblocks - 256 - 64;
        for (int col = tid; col < D; col += blockDim.x) {
            float s = 0.f;
            #pragma unroll
            for (int k = 0; k < KSHOT; k++) s += support[(size_t)(c * KSHOT + k) * D + col];
            s *= (1.f / KSHOT);
            g_smean[c * D + col] = s;
            g_smeanbf[c * D + col] = __float2bfloat16(s);
        }
    } else if (b < qblocks + 256 + 64 + 64 + 8) {
        // u = W^T b : 8 blocks x 64 k-cols, 4 j-groups of 128
        __shared__ float su[4][64];
        int k0 = (b - qblocks - 256 - 64 - 64) * 64;
        int kl = tid & 63, jg = tid >> 6;
        float acc = 0.f;
        #pragma unroll 8
        for (int j = jg * 128; j < jg * 128 + 128; j++)
            acc += bias[j] * W[(size_t)j * D + k0 + kl];
        su[jg][kl] = acc;
        __syncthreads();
        if (tid < 64) g_u[k0 + tid] = su[0][tid] + su[1][tid] + su[2][tid] + su[3][tid];
    } else {
        // ||b||^2
        float s = 0.f;
        for (int j = tid; j < D; j += 256) { float v = bias[j]; s += v * v; }
        #pragma unroll
        for (int o = 16; o > 0; o >>= 1) s += __shfl_xor_sync(0xffffffffu, s, o);
        __shared__ float red[8];
        if ((tid & 31) == 0) red[tid >> 5] = s;
        __syncthreads();
        if (tid == 0) {
            float t2 = 0.f;
            #pragma unroll
            for (int w = 0; w < 8; w++) t2 += red[w];
            g_bb = t2;
        }
    }
}

// ---------------- G = W^T W, split-K x4: grid (4 m, 8 n, 4 ks), fp32 partials ----------------
#define SM_G (2 * (ASZ + BSZ) * 2)
__global__ __launch_bounds__(256, 2) void g_gemm(int dummy) {
    extern __shared__ char smc[];
    __nv_bfloat16* sA = (__nv_bfloat16*)smc;
    __nv_bfloat16* sB = (__nv_bfloat16*)smc + 2 * ASZ;
    int tid = threadIdx.x;
    int m0 = blockIdx.x * 128, n0 = blockIdx.y * 64;
    int ks = blockIdx.z;                 // K chunk: cols ks*128 .. +128
    int warp = tid >> 5, lane = tid & 31;
    int wm = warp & 3, wn = warp >> 2;
    int g = lane >> 2, t4 = lane & 3;

    int aOff0 = (((wm * 32 + 0 + (lane & 15)) * SA + (lane >> 4) * 8)) * 2;
    int aOff1 = (((wm * 32 + 16 + (lane & 15)) * SA + (lane >> 4) * 8)) * 2;
    int bOff0 = (((wn * 32 + 0 + (lane & 7) + ((lane >> 4) << 3)) * SA + ((lane >> 3) & 1) * 8)) * 2;
    int bOff1 = (((wn * 32 + 16 + (lane & 7) + ((lane >> 4) << 3)) * SA + ((lane >> 3) & 1) * 8)) * 2;

    float acc[2][4][4];
    #pragma unroll
    for (int a = 0; a < 2; a++)
        #pragma unroll
        for (int b2 = 0; b2 < 4; b2++)
            #pragma unroll
            for (int c = 0; c < 4; c++) acc[a][b2][c] = 0.f;

    auto loadA = [&](int st, int kt) {
        #pragma unroll
        for (int j = 0; j < 4; j++) {
            int i = tid + j * 256, r = i >> 3, c8 = i & 7;
            cp_async16(sA + st * ASZ + r * SA + c8 * 8,
                       g_WbfT + (size_t)(m0 + r) * D + kt * 64 + c8 * 8);
        }
    };
    auto loadB = [&](int st, int kt) {
        #pragma unroll
        for (int j = 0; j < 2; j++) {
            int i = tid + j * 256, r = i >> 3, c8 = i & 7;
            cp_async16(sB + st * BSZ + r * SA + c8 * 8,
                       g_WbfT + (size_t)(n0 + r) * D + kt * 64 + c8 * 8);
        }
    };

    loadA(0, ks * 2); loadB(0, ks * 2); CP_COMMIT();
    loadA(1, ks * 2 + 1); loadB(1, ks * 2 + 1); CP_COMMIT();
    uint32_t sa0 = (uint32_t)__cvta_generic_to_shared(sA);
    uint32_t sb0 = (uint32_t)__cvta_generic_to_shared(sB);

    CP_WAIT(1); __syncthreads();
    tile_step(acc, sa0, sb0, aOff0, aOff1, bOff0, bOff1);
    CP_WAIT(0); __syncthreads();
    tile_step(acc, sa0 + ASZ * 2, sb0 + BSZ * 2, aOff0, aOff1, bOff0, bOff1);

    float* gp = g_Gpart + (size_t)ks * D * D;
    #pragma unroll
    for (int mf = 0; mf < 2; mf++) {
        int m = m0 + wm * 32 + mf * 16 + g;
        #pragma unroll
        for (int nf = 0; nf < 4; nf++) {
            int c = n0 + wn * 32 + nf * 8 + t4 * 2;
            float2 o0; o0.x = acc[mf][nf][0]; o0.y = acc[mf][nf][1];
            float2 o1; o1.x = acc[mf][nf][2]; o1.y = acc[mf][nf][3];
            *(float2*)(gp + (size_t)m * D + c) = o0;
            *(float2*)(gp + (size_t)(m + 8) * D + c) = o1;
        }
    }
}

// ---------------- gred: sum 4 G partials -> bf16 ----------------
__global__ void gred_kernel(int dummy) {
    int idx = (blockIdx.x * 256 + threadIdx.x) * 4;   // 256 blocks x 256 thr x 4 = 262144
    float4 a = *(const float4*)(g_Gpart + idx);
    float4 b = *(const float4*)(g_Gpart + D * D + idx);
    float4 c = *(const float4*)(g_Gpart + 2 * D * D + idx);
    float4 d = *(const float4*)(g_Gpart + 3 * D * D + idx);
    float s0 = a.x + b.x + c.x + d.x;
    float s1 = a.y + b.y + c.y + d.y;
    float s2 = a.z + b.z + c.z + d.z;
    float s3 = a.w + b.w + c.w + d.w;
    *(__nv_bfloat162*)(g_Gbf + idx)     = __floats2bfloat162_rn(s0, s1);
    *(__nv_bfloat162*)(g_Gbf + idx + 2) = __floats2bfloat162_rn(s2, s3);
}

// ---------------- R partials = smean_bf @ G chunk: grid (4 ntile, 2 ks) ----------------
#define SM_R (2 * (PA + PB) * 2)
__global__ __launch_bounds__(256) void r_gemm(int dummy) {
    extern __shared__ __nv_bfloat16 sm[];
    int tid = threadIdx.x;
    int n0 = blockIdx.x * 128;
    int ks = blockIdx.y;                // K chunk: j = ks*256 .. +256 (4 iters)
    int warp = tid >> 5, lane = tid & 31;
    int wm = warp & 1, wn = warp >> 1;
    int g = lane >> 2, t4 = lane & 3;

    int aOff0 = (((wm * 32 + 0 + (lane & 15)) * SA + (lane >> 4) * 8)) * 2;
    int aOff1 = (((wm * 32 + 16 + (lane & 15)) * SA + (lane >> 4) * 8)) * 2;
    int bOff0 = (((wn * 32 + 0 + (lane & 7) + ((lane >> 4) << 3)) * SA + ((lane >> 3) & 1) * 8)) * 2;
    int bOff1 = (((wn * 32 + 16 + (lane & 7) + ((lane >> 4) << 3)) * SA + ((lane >> 3) & 1) * 8)) * 2;

    auto load = [&](int st, int kt) {
        __nv_bfloat16* base = sm + st * (PA + PB);
        #pragma unroll
        for (int j = 0; j < 2; j++) {
            int i = tid + j * 256, r = i >> 3, c8 = i & 7;
            cp_async16(base + r * SA + c8 * 8, g_smeanbf + (size_t)r * D + kt * 64 + c8 * 8);
        }
        #pragma unroll
        for (int j = 0; j < 4; j++) {
            int i = tid + j * 256, r = i >> 3, c8 = i & 7;
            cp_async16(base + PA + r * SA + c8 * 8,
                       g_Gbf + (size_t)(n0 + r) * D + kt * 64 + c8 * 8);
        }
        CP_COMMIT();
    };

    float acc[2][4][4];
    #pragma unroll
    for (int a = 0; a < 2; a++)
        #pragma unroll
        for (int b2 = 0; b2 < 4; b2++)
            #pragma unroll
            for (int c = 0; c < 4; c++) acc[a][b2][c] = 0.f;

    uint32_t sm0 = (uint32_t)__cvta_generic_to_shared(sm);
    load(0, ks * 4);
    #pragma unroll 1
    for (int i = 0; i < 4; i++) {
        if (i + 1 < 4) { load((i + 1) & 1, ks * 4 + i + 1); CP_WAIT(1); } else { CP_WAIT(0); }
        __syncthreads();
        uint32_t st = sm0 + ((i & 1) * (PA + PB)) * 2;
        tile_step(acc, st, st + PA * 2, aOff0, aOff1, bOff0, bOff1);
        __syncthreads();
    }

    float* rp = g_Rpart + (size_t)ks * NWAY * D;
    #pragma unroll
    for (int mf = 0; mf < 2; mf++) {
        int m = wm * 32 + mf * 16 + g;
        #pragma unroll
        for (int nf = 0; nf < 4; nf++) {
            int c = n0 + wn * 32 + nf * 8 + t4 * 2;
            float2 o0; o0.x = acc[mf][nf][0]; o0.y = acc[mf][nf][1];
            float2 o1; o1.x = acc[mf][nf][2]; o1.y = acc[mf][nf][3];
            *(float2*)(rp + (size_t)m * D + c) = o0;
            *(float2*)(rp + (size_t)(m + 8) * D + c) = o1;
        }
    }
}

// ---------------- rred: R = sum partials + u -> bf16; pcterm = sGs - ||b||^2 ----------------
__global__ void rred_kernel(int dummy) {
    int c = blockIdx.x;        // class
    int tid = threadIdx.x;     // 256
    float pc = 0.f;
    #pragma unroll
    for (int h = 0; h < 2; h++) {
        int k = tid + h * 256;
        float v = g_Rpart[(size_t)c * D + k] + g_Rpart[(size_t)NWAY * D + (size_t)c * D + k];
        g_Bbig[(size_t)(512 + c) * D + k] = __float2bfloat16(v + g_u[k]);
        pc += g_smean[c * D + k] * v;
    }
    #pragma unroll
    for (int o = 16; o > 0; o >>= 1) pc += __shfl_xor_sync(0xffffffffu, pc, o);
    __shared__ float red[8];
    if ((tid & 31) == 0) red[tid >> 5] = pc;
    __syncthreads();
    if (tid == 0) {
        float t2 = 0.f;
        #pragma unroll
        for (int w = 0; w < 8; w++) t2 += red[w];
        g_pcterm[c] = t2 - g_bb;
    }
}

// ---------------- main GEMM: C = Qbf @ Bbig^T, LDSM-fed, 4-stage cp.async ----------------
#define SM_BIAS  (4 * (ASZ + BSZ) * 2)
#define SM_NORM  (SM_BIAS + 64 * 4)
#define SM_MAIN  (SM_NORM + 128 * 2 * 4)

__global__ __launch_bounds__(256, 2) void main_gemm(const float* __restrict__ bias, int M) {
    extern __shared__ char smc[];
    __nv_bfloat16* sA = (__nv_bfloat16*)smc;
    __nv_bfloat16* sB = (__nv_bfloat16*)smc + 4 * ASZ;
    float* sbias = (float*)(smc + SM_BIAS);
    float* snorm = (float*)(smc + SM_NORM);

    int tid = threadIdx.x;
    int m0 = blockIdx.x * 128;
    int nt = blockIdx.y;
    int n0 = nt * 64;
    int warp = tid >> 5, lane = tid & 31;
    int wm = warp & 3, wn = warp >> 2;
    int g = lane >> 2, t4 = lane & 3;

    if (nt < 8 && tid < 64) sbias[tid] = bias[n0 + tid];

    int aOff0 = (((wm * 32 + 0 + (lane & 15)) * SA + (lane >> 4) * 8)) * 2;
    int aOff1 = (((wm * 32 + 16 + (lane & 15)) * SA + (lane >> 4) * 8)) * 2;
    int bOff0 = (((wn * 32 + 0 + (lane & 7) + ((lane >> 4) << 3)) * SA + ((lane >> 3) & 1) * 8)) * 2;
    int bOff1 = (((wn * 32 + 16 + (lane & 7) + ((lane >> 4) << 3)) * SA + ((lane >> 3) & 1) * 8)) * 2;

    float acc[2][4][4];
    #pragma unroll
    for (int a = 0; a < 2; a++)
        #pragma unroll
        for (int b2 = 0; b2 < 4; b2++)
            #pragma unroll
            for (int c = 0; c < 4; c++) acc[a][b2][c] = 0.f;

    auto loadA = [&](int st, int kt) {
        #pragma unroll
        for (int j = 0; j < 4; j++) {
            int i = tid + j * 256, r = i >> 3, c8 = i & 7;
            int grow = m0 + r; if (grow >= M) grow = M - 1;
            cp_async16(sA + st * ASZ + r * SA + c8 * 8,
                       g_qbf + (size_t)grow * D + kt * 64 + c8 * 8);
        }
    };
    auto loadB = [&](int st, int kt) {
        #pragma unroll
        for (int j = 0; j < 2; j++) {
            int i = tid + j * 256, r = i >> 3, c8 = i & 7;
            cp_async16(sB + st * BSZ + r * SA + c8 * 8,
                       g_Bbig + (size_t)(n0 + r) * D + kt * 64 + c8 * 8);
        }
    };

    loadA(0, 0); loadB(0, 0); CP_COMMIT();
    loadA(1, 1); loadB(1, 1); CP_COMMIT();
    loadA(2, 2); loadB(2, 2); CP_COMMIT();

    uint32_t sa0 = (uint32_t)__cvta_generic_to_shared(sA);
    uint32_t sb0 = (uint32_t)__cvta_generic_to_shared(sB);

    #pragma unroll 1
    for (int kt = 0; kt < 8; kt++) {
        if (kt < 6) { CP_WAIT(2); } else if (kt == 6) { CP_WAIT(1); } else { CP_WAIT(0); }
        __syncthreads();
        if (kt + 3 < 8) { loadA((kt + 3) & 3, kt + 3); loadB((kt + 3) & 3, kt + 3); CP_COMMIT(); }
        tile_step(acc, sa0 + ((kt & 3) * ASZ) * 2, sb0 + ((kt & 3) * BSZ) * 2,
                  aOff0, aOff1, bOff0, bOff1);
    }

    if (nt < 8) {
        #pragma unroll
        for (int mf = 0; mf < 2; mf++) {
            float s0 = 0.f, s1 = 0.f;
            #pragma unroll
            for (int nf = 0; nf < 4; nf++) {
                int c = wn * 32 + nf * 8 + t4 * 2;
                float b0 = sbias[c], b1 = sbias[c + 1];
                float v;
                v = acc[mf][nf][0] + b0; s0 += v * v;
                v = acc[mf][nf][1] + b1; s0 += v * v;
                v = acc[mf][nf][2] + b0; s1 += v * v;
                v = acc[mf][nf][3] + b1; s1 += v * v;
            }
            s0 += __shfl_xor_sync(0xffffffffu, s0, 1);
            s0 += __shfl_xor_sync(0xffffffffu, s0, 2);
            s1 += __shfl_xor_sync(0xffffffffu, s1, 1);
            s1 += __shfl_xor_sync(0xffffffffu, s1, 2);
            if (t4 == 0) {
                int r = wm * 32 + mf * 16 + g;
                snorm[r * 2 + wn] = s0;
                snorm[(r + 8) * 2 + wn] = s1;
            }
        }
        __syncthreads();
        if (tid < 128 && m0 + tid < M)
            g_partial[(size_t)(m0 + tid) * 8 + nt] = snorm[tid * 2] + snorm[tid * 2 + 1];
    } else {
        #pragma unroll
        for (int mf = 0; mf < 2; mf++) {
            int r = wm * 32 + mf * 16 + g;
            #pragma unroll
            for (int nf = 0; nf < 4; nf++) {
                int c = wn * 32 + nf * 8 + t4 * 2;
                if (m0 + r < M) {
                    float2 o; o.x = acc[mf][nf][0]; o.y = acc[mf][nf][1];
                    *(float2*)(g_cross + (size_t)(m0 + r) * NWAY + c) = o;
                }
                if (m0 + r + 8 < M) {
                    float2 o; o.x = acc[mf][nf][2]; o.y = acc[mf][nf][3];
                    *(float2*)(g_cross + (size_t)(m0 + r + 8) * NWAY + c) = o;
                }
            }
        }
    }
}

// ---------------- combine: dist = nq + pcterm - 2*cross ----------------
__global__ void combine_kernel(float* __restrict__ out, int M) {
    __shared__ float snq[4];
    int tid = threadIdx.x;
    int q0 = blockIdx.x * 4;
    if (tid < 4 && q0 + tid < M) {
        float s = 0.f;
        #pragma unroll
        for (int t = 0; t < 8; t++) s += g_partial[(size_t)(q0 + tid) * 8 + t];
        snq[tid] = s;
    }
    __syncthreads();
    int q = q0 + (tid >> 6), c = tid & 63;
    if (q < M)
        out[(size_t)q * NWAY + c] = snq[tid >> 6] + g_pcterm[c]
                                    - 2.f * g_cross[(size_t)q * NWAY + c];
}

// ---------------- launch ----------------
extern "C" void kernel_launch(void* const* d_in, const int* in_sizes, int n_in,
                              void* d_out, int out_size) {
    const float* support = (const float*)d_in[0];
    const float* query   = (const float*)d_in[1];
    const float* W       = (const float*)d_in[2];
    const float* bias    = (const float*)d_in[3];
    int M = in_sizes[1] / D;
    if (M > MAXQ) M = MAXQ;
    float* out = (float*)d_out;

    cudaFuncSetAttribute(g_gemm,    cudaFuncAttributeMaxDynamicSharedMemorySize, SM_G);
    cudaFuncSetAttribute(r_gemm,    cudaFuncAttributeMaxDynamicSharedMemorySize, SM_R);
    cudaFuncSetAttribute(main_gemm, cudaFuncAttributeMaxDynamicSharedMemorySize, SM_MAIN);

    int qblocks = (int)(((size_t)M * D + 2047) / 2048);
    prep_kernel<<<qblocks + 256 + 64 + 64 + 8 + 1, 256>>>(query, W, support, bias, qblocks, M);
    g_gemm<<<dim3(4, 8, 4), 256, SM_G>>>(0);
    gred_kernel<<<256, 256>>>(0);
    r_gemm<<<dim3(4, 2), 256, SM_R>>>(0);
    rred_kernel<<<NWAY, 256>>>(0);
    main_gemm<<<dim3((M + 127) / 128, 9), 256, SM_MAIN>>>(bias, M);
    combine_kernel<<<(M + 3) / 4, 256>>>(out, M);
}

// round 10
// speedup vs baseline: 1.8150x; 1.1412x over previous
#include <cuda_runtime.h>
#include <cuda_bf16.h>
#include <cstdint>

#define D      512
#define NWAY   64
#define KSHOT  16
#define MAXQ   8192
#define SA     72            // smem K-stride (bf16): 144B rows, LDSM conflict-free
#define ASZ    (128 * SA)
#define BSZ    (64 * SA)
#define PA     (64 * SA)
#define PB     (128 * SA)

// ---------------- device scratch ----------------
__device__ __nv_bfloat16  g_smeanbf[NWAY * D];
__device__ __nv_bfloat16  g_Pbf[NWAY * D];
__device__ float          g_Ppart[4 * NWAY * D];      // split-K P partials (fp32)
__device__ float          g_Rpart[4 * NWAY * D];      // split-K R partials (fp32)
__device__ float          g_pcterm[NWAY];
__device__ __nv_bfloat16  g_qbf[(size_t)MAXQ * D];
__device__ __nv_bfloat16  g_Bbig[(512 + NWAY) * D];   // rows 0..511 W(bf16), 512..575 R
__device__ __nv_bfloat16  g_WbfT[D * D];              // WbfT[k, j] = W[j, k]
__device__ float          g_partial[(size_t)MAXQ * 8];
__device__ float          g_cross[(size_t)MAXQ * NWAY];

// ---------------- mma / ldmatrix / cp.async helpers ----------------
__device__ __forceinline__ void mma16816(float* c,
                                         uint32_t a0, uint32_t a1, uint32_t a2, uint32_t a3,
                                         uint32_t b0, uint32_t b1) {
    asm volatile(
        "mma.sync.aligned.m16n8k16.row.col.f32.bf16.bf16.f32 "
        "{%0,%1,%2,%3},{%4,%5,%6,%7},{%8,%9},{%0,%1,%2,%3};\n"
        : "+f"(c[0]), "+f"(c[1]), "+f"(c[2]), "+f"(c[3])
        : "r"(a0), "r"(a1), "r"(a2), "r"(a3), "r"(b0), "r"(b1));
}
__device__ __forceinline__ void ldsm4(uint32_t* r, uint32_t a) {
    asm volatile("ldmatrix.sync.aligned.m8n8.x4.shared.b16 {%0,%1,%2,%3}, [%4];"
                 : "=r"(r[0]), "=r"(r[1]), "=r"(r[2]), "=r"(r[3]) : "r"(a));
}
__device__ __forceinline__ void cp_async16(void* smem, const void* gmem) {
    uint32_t s = (uint32_t)__cvta_generic_to_shared(smem);
    asm volatile("cp.async.cg.shared.global [%0], [%1], 16;\n" :: "r"(s), "l"(gmem));
}
#define CP_COMMIT() asm volatile("cp.async.commit_group;\n")
#define CP_WAIT(n)  asm volatile("cp.async.wait_group %0;\n" :: "n"(n))

// One K=64 slab of a 32x32 warp tile: 2 m-frags x 4 n-frags, ldmatrix-fed.
__device__ __forceinline__ void tile_step(float acc[2][4][4], uint32_t aA, uint32_t aB,
                                          int aOff0, int aOff1, int bOff0, int bOff1) {
    #pragma unroll
    for (int kk = 0; kk < 64; kk += 16) {
        uint32_t br0[4], br1[4];
        ldsm4(br0, aB + bOff0 + kk * 2);
        ldsm4(br1, aB + bOff1 + kk * 2);
        #pragma unroll
        for (int mf = 0; mf < 2; mf++) {
            uint32_t ar[4];
            ldsm4(ar, aA + (mf ? aOff1 : aOff0) + kk * 2);
            mma16816(acc[mf][0], ar[0], ar[1], ar[2], ar[3], br0[0], br0[1]);
            mma16816(acc[mf][1], ar[0], ar[1], ar[2], ar[3], br0[2], br0[3]);
            mma16816(acc[mf][2], ar[0], ar[1], ar[2], ar[3], br1[0], br1[1]);
            mma16816(acc[mf][3], ar[0], ar[1], ar[2], ar[3], br1[2], br1[3]);
        }
    }
}

// ---------------- prep (256 thr): Q->bf16, W->bf16, W^T, smean(bf16) ----------------
__global__ void prep_kernel(const float* __restrict__ q, const float* __restrict__ W,
                            const float* __restrict__ support, int qblocks, int M) {
    int b = blockIdx.x;
    int tid = threadIdx.x;
    if (b < qblocks) {
        size_t total = (size_t)M * D;
        size_t base = (size_t)b * 2048 + tid * 8;
        if (base + 8 <= total) {
            float4 v0 = *(const float4*)(q + base);
            float4 v1 = *(const float4*)(q + base + 4);
            __nv_bfloat162 p0 = __floats2bfloat162_rn(v0.x, v0.y);
            __nv_bfloat162 p1 = __floats2bfloat162_rn(v0.z, v0.w);
            __nv_bfloat162 p2 = __floats2bfloat162_rn(v1.x, v1.y);
            __nv_bfloat162 p3 = __floats2bfloat162_rn(v1.z, v1.w);
            uint4 o;
            o.x = *(uint32_t*)&p0; o.y = *(uint32_t*)&p1;
            o.z = *(uint32_t*)&p2; o.w = *(uint32_t*)&p3;
            *(uint4*)(g_qbf + base) = o;
        } else {
            for (int e = 0; e < 8; e++)
                if (base + e < total) g_qbf[base + e] = __float2bfloat16(q[base + e]);
        }
    } else if (b < qblocks + 256) {
        int base = (b - qblocks) * 1024 + tid * 4;
        float4 v = *(const float4*)(W + base);
        *(__nv_bfloat162*)(g_Bbig + base)     = __floats2bfloat162_rn(v.x, v.y);
        *(__nv_bfloat162*)(g_Bbig + base + 2) = __floats2bfloat162_rn(v.z, v.w);
    } else if (b < qblocks + 256 + 64) {
        // W transpose 64x64 -> g_WbfT
        __shared__ float ts[64][68];
        int t = b - qblocks - 256;
        int r0 = (t >> 3) * 64, c0 = (t & 7) * 64;
        #pragma unroll
        for (int it = 0; it < 4; it++) {
            int r = (tid >> 4) + it * 16;
            float4 v = *(const float4*)(W + (size_t)(r0 + r) * D + c0 + (tid & 15) * 4);
            ts[r][(tid & 15) * 4 + 0] = v.x; ts[r][(tid & 15) * 4 + 1] = v.y;
            ts[r][(tid & 15) * 4 + 2] = v.z; ts[r][(tid & 15) * 4 + 3] = v.w;
        }
        __syncthreads();
        int kk = tid >> 2, jb = (tid & 3) * 16;
        #pragma unroll
        for (int e = 0; e < 16; e += 2) {
            *(__nv_bfloat162*)(g_WbfT + (size_t)(c0 + kk) * D + r0 + jb + e) =
                __floats2bfloat162_rn(ts[jb + e][kk], ts[jb + e + 1][kk]);
        }
    } else {
        // class means -> bf16
        int c = b - qblocks - 256 - 64;
        for (int col = tid; col < D; col += blockDim.x) {
            float s = 0.f;
            #pragma unroll
            for (int k = 0; k < KSHOT; k++) s += support[(size_t)(c * KSHOT + k) * D + col];
            g_smeanbf[c * D + col] = __float2bfloat16(s * (1.f / KSHOT));
        }
    }
}

// ---------------- small GEMM: C64xN128 tile, split-K (2 iters of 64), mode-selected ----------------
// mode 0: Ppart = smeanbf @ Bbig(W rows)^T ; mode 1: Rpart = Pbf @ WbfT^T
#define SM_P (2 * (PA + PB) * 2)
__global__ __launch_bounds__(256) void small_gemm(int mode) {
    extern __shared__ __nv_bfloat16 sm[];
    const __nv_bfloat16* Asrc = mode ? g_Pbf  : g_smeanbf;
    const __nv_bfloat16* Bsrc = mode ? g_WbfT : g_Bbig;
    float* Csrc = mode ? g_Rpart : g_Ppart;

    int tid = threadIdx.x;
    int n0 = blockIdx.x * 128;          // n tile
    int ks = blockIdx.y;                // K chunk: k = ks*128 .. +128
    int warp = tid >> 5, lane = tid & 31;
    int wm = warp & 1, wn = warp >> 1;
    int g = lane >> 2, t4 = lane & 3;

    int aOff0 = (((wm * 32 + 0 + (lane & 15)) * SA + (lane >> 4) * 8)) * 2;
    int aOff1 = (((wm * 32 + 16 + (lane & 15)) * SA + (lane >> 4) * 8)) * 2;
    int bOff0 = (((wn * 32 + 0 + (lane & 7) + ((lane >> 4) << 3)) * SA + ((lane >> 3) & 1) * 8)) * 2;
    int bOff1 = (((wn * 32 + 16 + (lane & 7) + ((lane >> 4) << 3)) * SA + ((lane >> 3) & 1) * 8)) * 2;

    auto load = [&](int st, int kt) {
        __nv_bfloat16* base = sm + st * (PA + PB);
        #pragma unroll
        for (int j = 0; j < 2; j++) {
            int i = tid + j * 256, r = i >> 3, c8 = i & 7;
            cp_async16(base + r * SA + c8 * 8, Asrc + (size_t)r * D + kt * 64 + c8 * 8);
        }
        #pragma unroll
        for (int j = 0; j < 4; j++) {
            int i = tid + j * 256, r = i >> 3, c8 = i & 7;
            cp_async16(base + PA + r * SA + c8 * 8,
                       Bsrc + (size_t)(n0 + r) * D + kt * 64 + c8 * 8);
        }
        CP_COMMIT();
    };

    float acc[2][4][4];
    #pragma unroll
    for (int a = 0; a < 2; a++)
        #pragma unroll
        for (int b2 = 0; b2 < 4; b2++)
            #pragma unroll
            for (int c = 0; c < 4; c++) acc[a][b2][c] = 0.f;

    uint32_t sm0 = (uint32_t)__cvta_generic_to_shared(sm);
    load(0, ks * 2);
    load(1, ks * 2 + 1);
    CP_WAIT(1); __syncthreads();
    tile_step(acc, sm0, sm0 + PA * 2, aOff0, aOff1, bOff0, bOff1);
    CP_WAIT(0); __syncthreads();
    tile_step(acc, sm0 + (PA + PB) * 2, sm0 + (2 * PA + PB) * 2, aOff0, aOff1, bOff0, bOff1);

    float* cp = Csrc + (size_t)ks * NWAY * D;
    #pragma unroll
    for (int mf = 0; mf < 2; mf++) {
        int m = wm * 32 + mf * 16 + g;
        #pragma unroll
        for (int nf = 0; nf < 4; nf++) {
            int c = n0 + wn * 32 + nf * 8 + t4 * 2;
            float2 o0; o0.x = acc[mf][nf][0]; o0.y = acc[mf][nf][1];
            float2 o1; o1.x = acc[mf][nf][2]; o1.y = acc[mf][nf][3];
            *(float2*)(cp + (size_t)m * D + c) = o0;
            *(float2*)(cp + (size_t)(m + 8) * D + c) = o1;
        }
    }
}

// ---------------- pred: P = sum(Ppart) + b -> Pbf; pcterm = ||p||^2 - 2 b.p ----------------
__global__ void pred_kernel(const float* __restrict__ bias) {
    int c = blockIdx.x;
    int tid = threadIdx.x;
    float pc = 0.f;
    #pragma unroll
    for (int h = 0; h < 2; h++) {
        int j = tid + h * 256;
        float v = g_Ppart[(size_t)c * D + j]
                + g_Ppart[(size_t)NWAY * D + (size_t)c * D + j]
                + g_Ppart[(size_t)2 * NWAY * D + (size_t)c * D + j]
                + g_Ppart[(size_t)3 * NWAY * D + (size_t)c * D + j]
                + bias[j];
        g_Pbf[c * D + j] = __float2bfloat16(v);
        pc += v * (v - 2.f * bias[j]);
    }
    #pragma unroll
    for (int o = 16; o > 0; o >>= 1) pc += __shfl_xor_sync(0xffffffffu, pc, o);
    __shared__ float red[8];
    if ((tid & 31) == 0) red[tid >> 5] = pc;
    __syncthreads();
    if (tid == 0) {
        float t2 = 0.f;
        #pragma unroll
        for (int w = 0; w < 8; w++) t2 += red[w];
        g_pcterm[c] = t2;
    }
}

// ---------------- rred: R = sum(Rpart) -> bf16 into Bbig rows 512.. ----------------
__global__ void rred_kernel(int dummy) {
    int c = blockIdx.x;
    int tid = threadIdx.x;
    #pragma unroll
    for (int h = 0; h < 2; h++) {
        int k = tid + h * 256;
        float v = g_Rpart[(size_t)c * D + k]
                + g_Rpart[(size_t)NWAY * D + (size_t)c * D + k]
                + g_Rpart[(size_t)2 * NWAY * D + (size_t)c * D + k]
                + g_Rpart[(size_t)3 * NWAY * D + (size_t)c * D + k];
        g_Bbig[(size_t)(512 + c) * D + k] = __float2bfloat16(v);
    }
}

// ---------------- main GEMM: C = Qbf @ Bbig^T, LDSM-fed, 4-stage cp.async ----------------
#define SM_BIAS  (4 * (ASZ + BSZ) * 2)
#define SM_NORM  (SM_BIAS + 64 * 4)
#define SM_MAIN  (SM_NORM + 128 * 2 * 4)

__global__ __launch_bounds__(256, 2) void main_gemm(const float* __restrict__ bias, int M) {
    extern __shared__ char smc[];
    __nv_bfloat16* sA = (__nv_bfloat16*)smc;
    __nv_bfloat16* sB = (__nv_bfloat16*)smc + 4 * ASZ;
    float* sbias = (float*)(smc + SM_BIAS);
    float* snorm = (float*)(smc + SM_NORM);

    int tid = threadIdx.x;
    int m0 = blockIdx.x * 128;
    int nt = blockIdx.y;
    int n0 = nt * 64;
    int warp = tid >> 5, lane = tid & 31;
    int wm = warp & 3, wn = warp >> 2;
    int g = lane >> 2, t4 = lane & 3;

    if (nt < 8 && tid < 64) sbias[tid] = bias[n0 + tid];

    int aOff0 = (((wm * 32 + 0 + (lane & 15)) * SA + (lane >> 4) * 8)) * 2;
    int aOff1 = (((wm * 32 + 16 + (lane & 15)) * SA + (lane >> 4) * 8)) * 2;
    int bOff0 = (((wn * 32 + 0 + (lane & 7) + ((lane >> 4) << 3)) * SA + ((lane >> 3) & 1) * 8)) * 2;
    int bOff1 = (((wn * 32 + 16 + (lane & 7) + ((lane >> 4) << 3)) * SA + ((lane >> 3) & 1) * 8)) * 2;

    float acc[2][4][4];
    #pragma unroll
    for (int a = 0; a < 2; a++)
        #pragma unroll
        for (int b2 = 0; b2 < 4; b2++)
            #pragma unroll
            for (int c = 0; c < 4; c++) acc[a][b2][c] = 0.f;

    auto loadA = [&](int st, int kt) {
        #pragma unroll
        for (int j = 0; j < 4; j++) {
            int i = tid + j * 256, r = i >> 3, c8 = i & 7;
            int grow = m0 + r; if (grow >= M) grow = M - 1;
            cp_async16(sA + st * ASZ + r * SA + c8 * 8,
                       g_qbf + (size_t)grow * D + kt * 64 + c8 * 8);
        }
    };
    auto loadB = [&](int st, int kt) {
        #pragma unroll
        for (int j = 0; j < 2; j++) {
            int i = tid + j * 256, r = i >> 3, c8 = i & 7;
            cp_async16(sB + st * BSZ + r * SA + c8 * 8,
                       g_Bbig + (size_t)(n0 + r) * D + kt * 64 + c8 * 8);
        }
    };

    loadA(0, 0); loadB(0, 0); CP_COMMIT();
    loadA(1, 1); loadB(1, 1); CP_COMMIT();
    loadA(2, 2); loadB(2, 2); CP_COMMIT();

    uint32_t sa0 = (uint32_t)__cvta_generic_to_shared(sA);
    uint32_t sb0 = (uint32_t)__cvta_generic_to_shared(sB);

    #pragma unroll 1
    for (int kt = 0; kt < 8; kt++) {
        if (kt < 6) { CP_WAIT(2); } else if (kt == 6) { CP_WAIT(1); } else { CP_WAIT(0); }
        __syncthreads();
        if (kt + 3 < 8) { loadA((kt + 3) & 3, kt + 3); loadB((kt + 3) & 3, kt + 3); CP_COMMIT(); }
        tile_step(acc, sa0 + ((kt & 3) * ASZ) * 2, sb0 + ((kt & 3) * BSZ) * 2,
                  aOff0, aOff1, bOff0, bOff1);
    }

    if (nt < 8) {
        #pragma unroll
        for (int mf = 0; mf < 2; mf++) {
            float s0 = 0.f, s1 = 0.f;
            #pragma unroll
            for (int nf = 0; nf < 4; nf++) {
                int c = wn * 32 + nf * 8 + t4 * 2;
                float b0 = sbias[c], b1 = sbias[c + 1];
                float v;
                v = acc[mf][nf][0] + b0; s0 += v * v;
                v = acc[mf][nf][1] + b1; s0 += v * v;
                v = acc[mf][nf][2] + b0; s1 += v * v;
                v = acc[mf][nf][3] + b1; s1 += v * v;
            }
            s0 += __shfl_xor_sync(0xffffffffu, s0, 1);
            s0 += __shfl_xor_sync(0xffffffffu, s0, 2);
            s1 += __shfl_xor_sync(0xffffffffu, s1, 1);
            s1 += __shfl_xor_sync(0xffffffffu, s1, 2);
            if (t4 == 0) {
                int r = wm * 32 + mf * 16 + g;
                snorm[r * 2 + wn] = s0;
                snorm[(r + 8) * 2 + wn] = s1;
            }
        }
        __syncthreads();
        if (tid < 128 && m0 + tid < M)
            g_partial[(size_t)(m0 + tid) * 8 + nt] = snorm[tid * 2] + snorm[tid * 2 + 1];
    } else {
        #pragma unroll
        for (int mf = 0; mf < 2; mf++) {
            int r = wm * 32 + mf * 16 + g;
            #pragma unroll
            for (int nf = 0; nf < 4; nf++) {
                int c = wn * 32 + nf * 8 + t4 * 2;
                if (m0 + r < M) {
                    float2 o; o.x = acc[mf][nf][0]; o.y = acc[mf][nf][1];
                    *(float2*)(g_cross + (size_t)(m0 + r) * NWAY + c) = o;
                }
                if (m0 + r + 8 < M) {
                    float2 o; o.x = acc[mf][nf][2]; o.y = acc[mf][nf][3];
                    *(float2*)(g_cross + (size_t)(m0 + r + 8) * NWAY + c) = o;
                }
            }
        }
    }
}

// ---------------- combine: dist = nq + pcterm - 2*cross ----------------
__global__ void combine_kernel(float* __restrict__ out, int M) {
    __shared__ float snq[4];
    int tid = threadIdx.x;
    int q0 = blockIdx.x * 4;
    if (tid < 4 && q0 + tid < M) {
        float s = 0.f;
        #pragma unroll
        for (int t = 0; t < 8; t++) s += g_partial[(size_t)(q0 + tid) * 8 + t];
        snq[tid] = s;
    }
    __syncthreads();
    int q = q0 + (tid >> 6), c = tid & 63;
    if (q < M)
        out[(size_t)q * NWAY + c] = snq[tid >> 6] + g_pcterm[c]
                                    - 2.f * g_cross[(size_t)q * NWAY + c];
}

// ---------------- launch ----------------
extern "C" void kernel_launch(void* const* d_in, const int* in_sizes, int n_in,
                              void* d_out, int out_size) {
    const float* support = (const float*)d_in[0];
    const float* query   = (const float*)d_in[1];
    const float* W       = (const float*)d_in[2];
    const float* bias    = (const float*)d_in[3];
    int M = in_sizes[1] / D;
    if (M > MAXQ) M = MAXQ;
    float* out = (float*)d_out;

    cudaFuncSetAttribute(small_gemm, cudaFuncAttributeMaxDynamicSharedMemorySize, SM_P);
    cudaFuncSetAttribute(main_gemm,  cudaFuncAttributeMaxDynamicSharedMemorySize, SM_MAIN);

    int qblocks = (int)(((size_t)M * D + 2047) / 2048);
    prep_kernel<<<qblocks + 256 + 64 + 64, 256>>>(query, W, support, qblocks, M);
    small_gemm<<<dim3(4, 4), 256, SM_P>>>(0);   // proj: Ppart
    pred_kernel<<<NWAY, 256>>>(bias);
    small_gemm<<<dim3(4, 4), 256, SM_P>>>(1);   // r2: Rpart
    rred_kernel<<<NWAY, 256>>>(0);
    main_gemm<<<dim3((M + 127) / 128, 9), 256, SM_MAIN>>>(bias, M);
    combine_kernel<<<(M + 3) / 4, 256>>>(out, M);
}

// round 11
// speedup vs baseline: 1.8448x; 1.0164x over previous
#include <cuda_runtime.h>
#include <cuda_bf16.h>
#include <cstdint>

#define D      512
#define NWAY   64
#define KSHOT  16
#define MAXQ   8192
#define SA     72            // smem K-stride (bf16): 144B rows, LDSM conflict-free
#define ASZ    (128 * SA)
#define BSZ    (64 * SA)
#define PA     (64 * SA)
#define PB     (128 * SA)

// ---------------- device scratch ----------------
__device__ __nv_bfloat16  g_smeanbf[NWAY * D];
__device__ float          g_Ppart[8 * NWAY * D];      // split-K P partials (fp32)
__device__ float          g_Rpart[8 * NWAY * D];      // split-K R partials (fp32)
__device__ float          g_pcpart[8 * NWAY];         // pcterm partials per j-chunk
__device__ __nv_bfloat16  g_qbf[(size_t)MAXQ * D];
__device__ __nv_bfloat16  g_Bbig[(512 + NWAY) * D];   // rows 0..511 W(bf16), 512..575 R
__device__ __nv_bfloat16  g_WbfT[D * D];              // WbfT[k, j] = W[j, k]
__device__ float          g_partial[(size_t)MAXQ * 8];
__device__ float          g_cross[(size_t)MAXQ * NWAY];

// ---------------- mma / ldmatrix / cp.async helpers ----------------
__device__ __forceinline__ void mma16816(float* c,
                                         uint32_t a0, uint32_t a1, uint32_t a2, uint32_t a3,
                                         uint32_t b0, uint32_t b1) {
    asm volatile(
        "mma.sync.aligned.m16n8k16.row.col.f32.bf16.bf16.f32 "
        "{%0,%1,%2,%3},{%4,%5,%6,%7},{%8,%9},{%0,%1,%2,%3};\n"
        : "+f"(c[0]), "+f"(c[1]), "+f"(c[2]), "+f"(c[3])
        : "r"(a0), "r"(a1), "r"(a2), "r"(a3), "r"(b0), "r"(b1));
}
__device__ __forceinline__ void ldsm4(uint32_t* r, uint32_t a) {
    asm volatile("ldmatrix.sync.aligned.m8n8.x4.shared.b16 {%0,%1,%2,%3}, [%4];"
                 : "=r"(r[0]), "=r"(r[1]), "=r"(r[2]), "=r"(r[3]) : "r"(a));
}
__device__ __forceinline__ void cp_async16(void* smem, const void* gmem) {
    uint32_t s = (uint32_t)__cvta_generic_to_shared(smem);
    asm volatile("cp.async.cg.shared.global [%0], [%1], 16;\n" :: "r"(s), "l"(gmem));
}
#define CP_COMMIT() asm volatile("cp.async.commit_group;\n")
#define CP_WAIT(n)  asm volatile("cp.async.wait_group %0;\n" :: "n"(n))

// One K=64 slab of a 32x32 warp tile: 2 m-frags x 4 n-frags, ldmatrix-fed.
__device__ __forceinline__ void tile_step(float acc[2][4][4], uint32_t aA, uint32_t aB,
                                          int aOff0, int aOff1, int bOff0, int bOff1) {
    #pragma unroll
    for (int kk = 0; kk < 64; kk += 16) {
        uint32_t br0[4], br1[4];
        ldsm4(br0, aB + bOff0 + kk * 2);
        ldsm4(br1, aB + bOff1 + kk * 2);
        #pragma unroll
        for (int mf = 0; mf < 2; mf++) {
            uint32_t ar[4];
            ldsm4(ar, aA + (mf ? aOff1 : aOff0) + kk * 2);
            mma16816(acc[mf][0], ar[0], ar[1], ar[2], ar[3], br0[0], br0[1]);
            mma16816(acc[mf][1], ar[0], ar[1], ar[2], ar[3], br0[2], br0[3]);
            mma16816(acc[mf][2], ar[0], ar[1], ar[2], ar[3], br1[0], br1[1]);
            mma16816(acc[mf][3], ar[0], ar[1], ar[2], ar[3], br1[2], br1[3]);
        }
    }
}

// ---------------- prep (256 thr): Q->bf16, W->bf16, W^T, smean(bf16) ----------------
__global__ void prep_kernel(const float* __restrict__ q, const float* __restrict__ W,
                            const float* __restrict__ support, int qblocks, int M) {
    int b = blockIdx.x;
    int tid = threadIdx.x;
    if (b < qblocks) {
        size_t total = (size_t)M * D;
        size_t base = (size_t)b * 2048 + tid * 8;
        if (base + 8 <= total) {
            float4 v0 = *(const float4*)(q + base);
            float4 v1 = *(const float4*)(q + base + 4);
            __nv_bfloat162 p0 = __floats2bfloat162_rn(v0.x, v0.y);
            __nv_bfloat162 p1 = __floats2bfloat162_rn(v0.z, v0.w);
            __nv_bfloat162 p2 = __floats2bfloat162_rn(v1.x, v1.y);
            __nv_bfloat162 p3 = __floats2bfloat162_rn(v1.z, v1.w);
            uint4 o;
            o.x = *(uint32_t*)&p0; o.y = *(uint32_t*)&p1;
            o.z = *(uint32_t*)&p2; o.w = *(uint32_t*)&p3;
            *(uint4*)(g_qbf + base) = o;
        } else {
            for (int e = 0; e < 8; e++)
                if (base + e < total) g_qbf[base + e] = __float2bfloat16(q[base + e]);
        }
    } else if (b < qblocks + 256) {
        int base = (b - qblocks) * 1024 + tid * 4;
        float4 v = *(const float4*)(W + base);
        *(__nv_bfloat162*)(g_Bbig + base)     = __floats2bfloat162_rn(v.x, v.y);
        *(__nv_bfloat162*)(g_Bbig + base + 2) = __floats2bfloat162_rn(v.z, v.w);
    } else if (b < qblocks + 256 + 64) {
        // W transpose 64x64 -> g_WbfT
        __shared__ float ts[64][68];
        int t = b - qblocks - 256;
        int r0 = (t >> 3) * 64, c0 = (t & 7) * 64;
        #pragma unroll
        for (int it = 0; it < 4; it++) {
            int r = (tid >> 4) + it * 16;
            float4 v = *(const float4*)(W + (size_t)(r0 + r) * D + c0 + (tid & 15) * 4);
            ts[r][(tid & 15) * 4 + 0] = v.x; ts[r][(tid & 15) * 4 + 1] = v.y;
            ts[r][(tid & 15) * 4 + 2] = v.z; ts[r][(tid & 15) * 4 + 3] = v.w;
        }
        __syncthreads();
        int kk = tid >> 2, jb = (tid & 3) * 16;
        #pragma unroll
        for (int e = 0; e < 16; e += 2) {
            *(__nv_bfloat162*)(g_WbfT + (size_t)(c0 + kk) * D + r0 + jb + e) =
                __floats2bfloat162_rn(ts[jb + e][kk], ts[jb + e + 1][kk]);
        }
    } else {
        // class means -> bf16
        int c = b - qblocks - 256 - 64;
        for (int col = tid; col < D; col += blockDim.x) {
            float s = 0.f;
            #pragma unroll
            for (int k = 0; k < KSHOT; k++) s += support[(size_t)(c * KSHOT + k) * D + col];
            g_smeanbf[c * D + col] = __float2bfloat16(s * (1.f / KSHOT));
        }
    }
}

// ---------------- proj: Ppart[ks] = smeanbf @ W^T (one 64-k chunk per block) ----------------
// grid (4 j-tiles of 128, 8 ks). P[c][j] = sum_k smean[c][k] W[j][k].
__global__ __launch_bounds__(256) void proj_gemm(int dummy) {
    __shared__ __nv_bfloat16 sA[PA];
    __shared__ __nv_bfloat16 sB[PB];
    int tid = threadIdx.x;
    int n0 = blockIdx.x * 128;    // j tile
    int ks = blockIdx.y;          // k chunk
    int warp = tid >> 5, lane = tid & 31;
    int wm = warp & 1, wn = warp >> 1;
    int g = lane >> 2, t4 = lane & 3;

    int aOff0 = (((wm * 32 + 0 + (lane & 15)) * SA + (lane >> 4) * 8)) * 2;
    int aOff1 = (((wm * 32 + 16 + (lane & 15)) * SA + (lane >> 4) * 8)) * 2;
    int bOff0 = (((wn * 32 + 0 + (lane & 7) + ((lane >> 4) << 3)) * SA + ((lane >> 3) & 1) * 8)) * 2;
    int bOff1 = (((wn * 32 + 16 + (lane & 7) + ((lane >> 4) << 3)) * SA + ((lane >> 3) & 1) * 8)) * 2;

    #pragma unroll
    for (int j = 0; j < 2; j++) {
        int i = tid + j * 256, r = i >> 3, c8 = i & 7;
        cp_async16(sA + r * SA + c8 * 8, g_smeanbf + (size_t)r * D + ks * 64 + c8 * 8);
    }
    #pragma unroll
    for (int j = 0; j < 4; j++) {
        int i = tid + j * 256, r = i >> 3, c8 = i & 7;
        cp_async16(sB + r * SA + c8 * 8, g_Bbig + (size_t)(n0 + r) * D + ks * 64 + c8 * 8);
    }
    CP_COMMIT();

    float acc[2][4][4];
    #pragma unroll
    for (int a = 0; a < 2; a++)
        #pragma unroll
        for (int b2 = 0; b2 < 4; b2++)
            #pragma unroll
            for (int c = 0; c < 4; c++) acc[a][b2][c] = 0.f;

    CP_WAIT(0); __syncthreads();
    tile_step(acc, (uint32_t)__cvta_generic_to_shared(sA),
              (uint32_t)__cvta_generic_to_shared(sB), aOff0, aOff1, bOff0, bOff1);

    float* cp = g_Ppart + (size_t)ks * NWAY * D;
    #pragma unroll
    for (int mf = 0; mf < 2; mf++) {
        int m = wm * 32 + mf * 16 + g;
        #pragma unroll
        for (int nf = 0; nf < 4; nf++) {
            int c = n0 + wn * 32 + nf * 8 + t4 * 2;
            float2 o0; o0.x = acc[mf][nf][0]; o0.y = acc[mf][nf][1];
            float2 o1; o1.x = acc[mf][nf][2]; o1.y = acc[mf][nf][3];
            *(float2*)(cp + (size_t)m * D + c) = o0;
            *(float2*)(cp + (size_t)(m + 8) * D + c) = o1;
        }
    }
}

// ---------------- r2: Rpart[js] = P @ W over j-chunk; builds P from Ppart+bias in-kernel ----------------
// grid (4 kcol-tiles of 128, 8 js). R[c][k] = sum_j P[c][j] W[j][k]; B rows = WbfT.
// n0==0 blocks also emit pcterm partial over their j-chunk: sum_j v*(v-2b_j).
__global__ __launch_bounds__(256) void r2_gemm(const float* __restrict__ bias) {
    __shared__ __nv_bfloat16 sA[PA];
    __shared__ __nv_bfloat16 sB[PB];
    int tid = threadIdx.x;
    int n0 = blockIdx.x * 128;    // k-col tile of R
    int js = blockIdx.y;          // j chunk
    int warp = tid >> 5, lane = tid & 31;
    int wm = warp & 1, wn = warp >> 1;
    int g = lane >> 2, t4 = lane & 3;

    int aOff0 = (((wm * 32 + 0 + (lane & 15)) * SA + (lane >> 4) * 8)) * 2;
    int aOff1 = (((wm * 32 + 16 + (lane & 15)) * SA + (lane >> 4) * 8)) * 2;
    int bOff0 = (((wn * 32 + 0 + (lane & 7) + ((lane >> 4) << 3)) * SA + ((lane >> 3) & 1) * 8)) * 2;
    int bOff1 = (((wn * 32 + 16 + (lane & 7) + ((lane >> 4) << 3)) * SA + ((lane >> 3) & 1) * 8)) * 2;

    #pragma unroll
    for (int j = 0; j < 4; j++) {
        int i = tid + j * 256, r = i >> 3, c8 = i & 7;
        cp_async16(sB + r * SA + c8 * 8, g_WbfT + (size_t)(n0 + r) * D + js * 64 + c8 * 8);
    }
    CP_COMMIT();

    // Build A tile: P[row][j] = sum_{kp} Ppart[kp][row][j] + bias[j]; thread = (row, 16 j)
    int row = tid >> 2, jq = (tid & 3) * 16;
    float pc = 0.f;
    #pragma unroll
    for (int g4 = 0; g4 < 4; g4++) {
        int j = js * 64 + jq + g4 * 4;
        float4 v = *(const float4*)(bias + j);
        #pragma unroll
        for (int kp = 0; kp < 8; kp++) {
            const float4 pp = *(const float4*)(g_Ppart + (size_t)kp * NWAY * D + (size_t)row * D + j);
            v.x += pp.x; v.y += pp.y; v.z += pp.z; v.w += pp.w;
        }
        float4 b4 = *(const float4*)(bias + j);
        pc += v.x * (v.x - 2.f * b4.x) + v.y * (v.y - 2.f * b4.y)
            + v.z * (v.z - 2.f * b4.z) + v.w * (v.w - 2.f * b4.w);
        *(__nv_bfloat162*)(sA + row * SA + jq + g4 * 4)     = __floats2bfloat162_rn(v.x, v.y);
        *(__nv_bfloat162*)(sA + row * SA + jq + g4 * 4 + 2) = __floats2bfloat162_rn(v.z, v.w);
    }
    if (blockIdx.x == 0) {
        pc += __shfl_xor_sync(0xffffffffu, pc, 1);
        pc += __shfl_xor_sync(0xffffffffu, pc, 2);
        if ((tid & 3) == 0) g_pcpart[js * NWAY + row] = pc;
    }

    float acc[2][4][4];
    #pragma unroll
    for (int a = 0; a < 2; a++)
        #pragma unroll
        for (int b2 = 0; b2 < 4; b2++)
            #pragma unroll
            for (int c = 0; c < 4; c++) acc[a][b2][c] = 0.f;

    CP_WAIT(0); __syncthreads();
    tile_step(acc, (uint32_t)__cvta_generic_to_shared(sA),
              (uint32_t)__cvta_generic_to_shared(sB), aOff0, aOff1, bOff0, bOff1);

    float* cp = g_Rpart + (size_t)js * NWAY * D;
    #pragma unroll
    for (int mf = 0; mf < 2; mf++) {
        int m = wm * 32 + mf * 16 + g;
        #pragma unroll
        for (int nf = 0; nf < 4; nf++) {
            int c = n0 + wn * 32 + nf * 8 + t4 * 2;
            float2 o0; o0.x = acc[mf][nf][0]; o0.y = acc[mf][nf][1];
            float2 o1; o1.x = acc[mf][nf][2]; o1.y = acc[mf][nf][3];
            *(float2*)(cp + (size_t)m * D + c) = o0;
            *(float2*)(cp + (size_t)(m + 8) * D + c) = o1;
        }
    }
}

// ---------------- rred: R = sum(8 Rpart) -> bf16 into Bbig rows 512.. ----------------
__global__ void rred_kernel(int dummy) {
    int c = blockIdx.x;
    int tid = threadIdx.x;
    #pragma unroll
    for (int h = 0; h < 2; h++) {
        int k = tid + h * 256;
        float v = 0.f;
        #pragma unroll
        for (int js = 0; js < 8; js++)
            v += g_Rpart[(size_t)js * NWAY * D + (size_t)c * D + k];
        g_Bbig[(size_t)(512 + c) * D + k] = __float2bfloat16(v);
    }
}

// ---------------- main GEMM: C = Qbf @ Bbig^T, LDSM-fed, 4-stage cp.async ----------------
#define SM_BIAS  (4 * (ASZ + BSZ) * 2)
#define SM_NORM  (SM_BIAS + 64 * 4)
#define SM_MAIN  (SM_NORM + 128 * 2 * 4)

__global__ __launch_bounds__(256, 2) void main_gemm(const float* __restrict__ bias, int M,
                                                    int ntbase) {
    extern __shared__ char smc[];
    __nv_bfloat16* sA = (__nv_bfloat16*)smc;
    __nv_bfloat16* sB = (__nv_bfloat16*)smc + 4 * ASZ;
    float* sbias = (float*)(smc + SM_BIAS);
    float* snorm = (float*)(smc + SM_NORM);

    int tid = threadIdx.x;
    int m0 = blockIdx.x * 128;
    int nt = ntbase + blockIdx.y;
    int n0 = nt * 64;
    int warp = tid >> 5, lane = tid & 31;
    int wm = warp & 3, wn = warp >> 2;
    int g = lane >> 2, t4 = lane & 3;

    if (nt < 8 && tid < 64) sbias[tid] = bias[n0 + tid];

    int aOff0 = (((wm * 32 + 0 + (lane & 15)) * SA + (lane >> 4) * 8)) * 2;
    int aOff1 = (((wm * 32 + 16 + (lane & 15)) * SA + (lane >> 4) * 8)) * 2;
    int bOff0 = (((wn * 32 + 0 + (lane & 7) + ((lane >> 4) << 3)) * SA + ((lane >> 3) & 1) * 8)) * 2;
    int bOff1 = (((wn * 32 + 16 + (lane & 7) + ((lane >> 4) << 3)) * SA + ((lane >> 3) & 1) * 8)) * 2;

    float acc[2][4][4];
    #pragma unroll
    for (int a = 0; a < 2; a++)
        #pragma unroll
        for (int b2 = 0; b2 < 4; b2++)
            #pragma unroll
            for (int c = 0; c < 4; c++) acc[a][b2][c] = 0.f;

    auto loadA = [&](int st, int kt) {
        #pragma unroll
        for (int j = 0; j < 4; j++) {
            int i = tid + j * 256, r = i >> 3, c8 = i & 7;
            int grow = m0 + r; if (grow >= M) grow = M - 1;
            cp_async16(sA + st * ASZ + r * SA + c8 * 8,
                       g_qbf + (size_t)grow * D + kt * 64 + c8 * 8);
        }
    };
    auto loadB = [&](int st, int kt) {
        #pragma unroll
        for (int j = 0; j < 2; j++) {
            int i = tid + j * 256, r = i >> 3, c8 = i & 7;
            cp_async16(sB + st * BSZ + r * SA + c8 * 8,
                       g_Bbig + (size_t)(n0 + r) * D + kt * 64 + c8 * 8);
        }
    };

    loadA(0, 0); loadB(0, 0); CP_COMMIT();
    loadA(1, 1); loadB(1, 1); CP_COMMIT();
    loadA(2, 2); loadB(2, 2); CP_COMMIT();

    uint32_t sa0 = (uint32_t)__cvta_generic_to_shared(sA);
    uint32_t sb0 = (uint32_t)__cvta_generic_to_shared(sB);

    #pragma unroll 1
    for (int kt = 0; kt < 8; kt++) {
        if (kt < 6) { CP_WAIT(2); } else if (kt == 6) { CP_WAIT(1); } else { CP_WAIT(0); }
        __syncthreads();
        if (kt + 3 < 8) { loadA((kt + 3) & 3, kt + 3); loadB((kt + 3) & 3, kt + 3); CP_COMMIT(); }
        tile_step(acc, sa0 + ((kt & 3) * ASZ) * 2, sb0 + ((kt & 3) * BSZ) * 2,
                  aOff0, aOff1, bOff0, bOff1);
    }

    if (nt < 8) {
        #pragma unroll
        for (int mf = 0; mf < 2; mf++) {
            float s0 = 0.f, s1 = 0.f;
            #pragma unroll
            for (int nf = 0; nf < 4; nf++) {
                int c = wn * 32 + nf * 8 + t4 * 2;
                float b0 = sbias[c], b1 = sbias[c + 1];
                float v;
                v = acc[mf][nf][0] + b0; s0 += v * v;
                v = acc[mf][nf][1] + b1; s0 += v * v;
                v = acc[mf][nf][2] + b0; s1 += v * v;
                v = acc[mf][nf][3] + b1; s1 += v * v;
            }
            s0 += __shfl_xor_sync(0xffffffffu, s0, 1);
            s0 += __shfl_xor_sync(0xffffffffu, s0, 2);
            s1 += __shfl_xor_sync(0xffffffffu, s1, 1);
            s1 += __shfl_xor_sync(0xffffffffu, s1, 2);
            if (t4 == 0) {
                int r = wm * 32 + mf * 16 + g;
                snorm[r * 2 + wn] = s0;
                snorm[(r + 8) * 2 + wn] = s1;
            }
        }
        __syncthreads();
        if (tid < 128 && m0 + tid < M)
            g_partial[(size_t)(m0 + tid) * 8 + nt] = snorm[tid * 2] + snorm[tid * 2 + 1];
    } else {
        #pragma unroll
        for (int mf = 0; mf < 2; mf++) {
            int r = wm * 32 + mf * 16 + g;
            #pragma unroll
            for (int nf = 0; nf < 4; nf++) {
                int c = wn * 32 + nf * 8 + t4 * 2;
                if (m0 + r < M) {
                    float2 o; o.x = acc[mf][nf][0]; o.y = acc[mf][nf][1];
                    *(float2*)(g_cross + (size_t)(m0 + r) * NWAY + c) = o;
                }
                if (m0 + r + 8 < M) {
                    float2 o; o.x = acc[mf][nf][2]; o.y = acc[mf][nf][3];
                    *(float2*)(g_cross + (size_t)(m0 + r + 8) * NWAY + c) = o;
                }
            }
        }
    }
}

// ---------------- combine: dist = nq + pcterm - 2*cross ----------------
__global__ void combine_kernel(float* __restrict__ out, int M) {
    __shared__ float snq[4];
    int tid = threadIdx.x;
    int q0 = blockIdx.x * 4;
    if (tid < 4 && q0 + tid < M) {
        float s = 0.f;
        #pragma unroll
        for (int t = 0; t < 8; t++) s += g_partial[(size_t)(q0 + tid) * 8 + t];
        snq[tid] = s;
    }
    __syncthreads();
    int q = q0 + (tid >> 6), c = tid & 63;
    if (q < M) {
        float pc = 0.f;
        #pragma unroll
        for (int js = 0; js < 8; js++) pc += g_pcpart[js * NWAY + c];
        out[(size_t)q * NWAY + c] = snq[tid >> 6] + pc
                                    - 2.f * g_cross[(size_t)q * NWAY + c];
    }
}

// ---------------- launch ----------------
extern "C" void kernel_launch(void* const* d_in, const int* in_sizes, int n_in,
                              void* d_out, int out_size) {
    const float* support = (const float*)d_in[0];
    const float* query   = (const float*)d_in[1];
    const float* W       = (const float*)d_in[2];
    const float* bias    = (const float*)d_in[3];
    int M = in_sizes[1] / D;
    if (M > MAXQ) M = MAXQ;
    float* out = (float*)d_out;
    int mblocks = (M + 127) / 128;

    cudaFuncSetAttribute(main_gemm, cudaFuncAttributeMaxDynamicSharedMemorySize, SM_MAIN);

    // Fork-join concurrency (capturable): prototype chain || main_norm.
    cudaStream_t s2 = 0;
    cudaEvent_t eFork = 0, eJoin = 0;
    bool par = (cudaStreamCreateWithFlags(&s2, cudaStreamNonBlocking) == cudaSuccess);
    if (par) par = (cudaEventCreateWithFlags(&eFork, cudaEventDisableTiming) == cudaSuccess);
    if (par) par = (cudaEventCreateWithFlags(&eJoin, cudaEventDisableTiming) == cudaSuccess);

    int qblocks = (int)(((size_t)M * D + 2047) / 2048);
    prep_kernel<<<qblocks + 256 + 64 + 64, 256>>>(query, W, support, qblocks, M);

    if (par) {
        cudaEventRecord(eFork, 0);
        cudaStreamWaitEvent(s2, eFork, 0);
        proj_gemm<<<dim3(4, 8), 256, 0, s2>>>(0);
        r2_gemm<<<dim3(4, 8), 256, 0, s2>>>(bias);
        rred_kernel<<<NWAY, 256, 0, s2>>>(0);
        cudaEventRecord(eJoin, s2);
        main_gemm<<<dim3(mblocks, 8), 256, SM_MAIN>>>(bias, M, 0);   // norm (concurrent)
        cudaStreamWaitEvent(0, eJoin, 0);
        main_gemm<<<dim3(mblocks, 1), 256, SM_MAIN>>>(bias, M, 8);   // cross
    } else {
        proj_gemm<<<dim3(4, 8), 256>>>(0);
        r2_gemm<<<dim3(4, 8), 256>>>(bias);
        rred_kernel<<<NWAY, 256>>>(0);
        main_gemm<<<dim3(mblocks, 8), 256, SM_MAIN>>>(bias, M, 0);
        main_gemm<<<dim3(mblocks, 1), 256, SM_MAIN>>>(bias, M, 8);
    }
    combine_kernel<<<(M + 3) / 4, 256>>>(out, M);
}